// round 1
// baseline (speedup 1.0000x reference)
#include <cuda_runtime.h>
#include <cstddef>
#include <cstdint>

// ---------------- problem dims ----------------
#define B_  4
#define C_  64
#define H_  128
#define W_  128
#define HS  64            // fg half-size
#define NP  4096          // 64*64 patches / positions
#define KP  576           // 64ch * 3*3
#define JB  1024          // 64ch * 4*4 (bg patch columns)
#define MC  65536         // msfa positions: 4*128*128
#define KC  576           // msfa conv K

// ---------------- scratch (static device globals; no allocation) ----------
static __device__ __align__(16) float g_fgs[(size_t)B_ * C_ * HS * HS];       // 4 MB
static __device__ __align__(16) float g_P[(size_t)B_ * KP * NP];              // 37.7 MB
static __device__ __align__(16) float g_G[(size_t)B_ * NP * NP];              // 268 MB (score->attn in place)
static __device__ __align__(16) float g_inv[B_ * NP];
static __device__ __align__(16) float g_Bg[(size_t)B_ * NP * JB];             // 67 MB
static __device__ __align__(16) float g_U[(size_t)B_ * JB * NP];              // 67 MB  (layout [b][j][q])
static __device__ __align__(16) float g_x[(size_t)B_ * C_ * H_ * W_];         // 16 MB  (RAL out, NCHW)
static __device__ __align__(16) float g_Xcol[(size_t)KC * MC];                // 151 MB
static __device__ __align__(16) float g_h[(size_t)MC * C_];                   // 16 MB  ((m,c) layout)
static __device__ __align__(16) float g_wmap[(size_t)MC * 4];                 // 1 MB
static __device__ __align__(16) float g_acc[(size_t)MC * C_];                 // 16 MB
static __device__ __align__(16) float g_WT[KC * C_];                          // repacked weights

// ---------------- bilinear half-resize (align_corners) --------------------
__global__ void k_resize(const float* __restrict__ fg)
{
    int idx = blockIdx.x * 256 + threadIdx.x;
    if (idx >= B_ * C_ * HS * HS) return;
    int x = idx & 63, y = (idx >> 6) & 63;
    int bc = idx >> 12;
    const float* src = fg + (size_t)bc * H_ * W_;

    float cy = (float)y * (127.0f / 63.0f);
    float cx = (float)x * (127.0f / 63.0f);
    int iy = (int)cy; if (iy > 127) iy = 127;
    int ix = (int)cx; if (ix > 127) ix = 127;
    int iy1 = min(iy + 1, 127), ix1 = min(ix + 1, 127);
    float wy = cy - (float)iy, wx = cx - (float)ix;

    float v00 = src[iy * 128 + ix],  v01 = src[iy * 128 + ix1];
    float v10 = src[iy1 * 128 + ix], v11 = src[iy1 * 128 + ix1];
    g_fgs[idx] = (1.f - wy) * ((1.f - wx) * v00 + wx * v01)
               +        wy  * ((1.f - wx) * v10 + wx * v11);
}

// ---------------- fg im2col: P[b][k][q], k=c*9+dy*3+dx, q=y*64+x ----------
__global__ void k_build_P()
{
    size_t idx = (size_t)blockIdx.x * 256 + threadIdx.x;
    if (idx >= (size_t)B_ * KP * NP) return;
    int q = (int)(idx & (NP - 1));
    int k = (int)((idx >> 12) % KP);
    int b = (int)(idx / ((size_t)KP * NP));
    int x = q & 63, y = q >> 6;
    int dx = k % 3, dy = (k / 3) % 3, c = k / 9;
    int sy = y + dy - 1, sx = x + dx - 1;
    float v = 0.f;
    if ((unsigned)sy < 64u && (unsigned)sx < 64u)
        v = g_fgs[(((size_t)b * C_ + c) * 64 + sy) * 64 + sx];
    g_P[idx] = v;
}

// ---------------- bg im2col: Bg[b][p][j], p=py*64+px, j=c*16+ky*4+kx -----
__global__ void k_build_Bg(const float* __restrict__ bg)
{
    size_t idx = (size_t)blockIdx.x * 256 + threadIdx.x;
    if (idx >= (size_t)B_ * NP * JB) return;
    int j = (int)(idx & 1023);
    int p = (int)((idx >> 10) & 4095);
    int b = (int)(idx >> 22);
    int c = j >> 4, ky = (j >> 2) & 3, kx = j & 3;
    int py = p >> 6, px = p & 63;
    int sy = 2 * py + ky - 1, sx = 2 * px + kx - 1;
    float v = 0.f;
    if ((unsigned)sy < 128u && (unsigned)sx < 128u)
        v = bg[(((size_t)b * 64 + c) * 128 + sy) * 128 + sx];
    g_Bg[idx] = v;
}

// ---------------- generic TN SGEMM: C[m,n] = sum_k A[k,m]*B[k,n] ----------
// epi: 0 = store, 1 = relu(v+bias[n]) store, 2 = relu(v+bias[n])*wmap[m*4+wsel], accumulate
template<int BM, int BN, int BK, int TM, int TN>
__global__ void __launch_bounds__((BM / TM) * (BN / TN))
k_gemm(const float* __restrict__ A, const float* __restrict__ B, float* __restrict__ C,
       int K, int lda, int ldb, int ldc,
       size_t sA, size_t sB, size_t sC,
       int epi, const float* __restrict__ bias,
       const float* __restrict__ wmap, int wsel, int accum)
{
    constexpr int THREADS = (BM / TM) * (BN / TN);
    __shared__ float As[BK][BM];
    __shared__ float Bs[BK][BN];
    A += (size_t)blockIdx.z * sA;
    B += (size_t)blockIdx.z * sB;
    C += (size_t)blockIdx.z * sC;
    const int m0 = blockIdx.y * BM, n0 = blockIdx.x * BN;
    const int tid = threadIdx.x;
    const int tx = tid % (BN / TN), ty = tid / (BN / TN);

    float acc[TM][TN];
#pragma unroll
    for (int i = 0; i < TM; i++)
#pragma unroll
        for (int j = 0; j < TN; j++) acc[i][j] = 0.f;

    constexpr int AV = (BK * BM) / (THREADS * 4);
    constexpr int BV = (BK * BN) / (THREADS * 4);

    for (int kt = 0; kt < K; kt += BK) {
#pragma unroll
        for (int i = 0; i < AV; i++) {
            int idx = tid + i * THREADS;
            int kk = idx / (BM / 4), mm = (idx % (BM / 4)) * 4;
            *(float4*)&As[kk][mm] =
                *(const float4*)(A + (size_t)(kt + kk) * lda + m0 + mm);
        }
#pragma unroll
        for (int i = 0; i < BV; i++) {
            int idx = tid + i * THREADS;
            int kk = idx / (BN / 4), nn = (idx % (BN / 4)) * 4;
            *(float4*)&Bs[kk][nn] =
                *(const float4*)(B + (size_t)(kt + kk) * ldb + n0 + nn);
        }
        __syncthreads();
#pragma unroll
        for (int k = 0; k < BK; k++) {
            float af[TM], bf[TN];
#pragma unroll
            for (int i = 0; i < TM; i++) af[i] = As[k][ty * TM + i];
#pragma unroll
            for (int j = 0; j < TN; j++) bf[j] = Bs[k][tx * TN + j];
#pragma unroll
            for (int i = 0; i < TM; i++)
#pragma unroll
                for (int j = 0; j < TN; j++) acc[i][j] = fmaf(af[i], bf[j], acc[i][j]);
        }
        __syncthreads();
    }

#pragma unroll
    for (int i = 0; i < TM; i++) {
        int m = m0 + ty * TM + i;
#pragma unroll
        for (int j = 0; j < TN; j++) {
            int n = n0 + tx * TN + j;
            size_t o = (size_t)m * ldc + n;
            float v = acc[i][j];
            if (epi == 0) {
                C[o] = v;
            } else {
                v = fmaxf(v + bias[n], 0.f);
                if (epi == 1) {
                    C[o] = v;
                } else {
                    float wv = wmap[(size_t)m * 4 + wsel] * v;
                    C[o] = accum ? (C[o] + wv) : wv;
                }
            }
        }
    }
}

// ---------------- norms from diag(G) --------------------------------------
__global__ void k_norms()
{
    int idx = blockIdx.x * 256 + threadIdx.x;
    if (idx >= B_ * NP) return;
    int b = idx >> 12, p = idx & (NP - 1);
    float d = g_G[((size_t)b * NP + p) * NP + p];
    float n = sqrtf(fmaxf(d, 0.f));
    g_inv[idx] = 1.0f / fmaxf(n, 1e-4f);
}

// ---------------- column softmax over p (in place on G), clip 1e-8 -------
__global__ void k_softmax()   // grid (128,1,4), block (32,8)
{
    __shared__ float red[8][32];
    const int b = blockIdx.z;
    float* Gb = g_G + (size_t)b * NP * NP;
    const float* invb = g_inv + b * NP;
    const int tx = threadIdx.x, ty = threadIdx.y;
    const int q = blockIdx.x * 32 + tx;

    // pass 1: max of inv[p]*G[p,q]
    float m = -3.0e38f;
    for (int p = ty; p < NP; p += 8)
        m = fmaxf(m, invb[p] * Gb[(size_t)p * NP + q]);
    red[ty][tx] = m;
    __syncthreads();
    float mall = red[0][tx];
#pragma unroll
    for (int i = 1; i < 8; i++) mall = fmaxf(mall, red[i][tx]);
    __syncthreads();
    mall *= 10.f;

    // pass 2: exp, store exp into G, accumulate sum
    float s = 0.f;
    for (int p = ty; p < NP; p += 8) {
        size_t o = (size_t)p * NP + q;
        float e = __expf(10.f * invb[p] * Gb[o] - mall);
        Gb[o] = e;
        s += e;
    }
    red[ty][tx] = s;
    __syncthreads();
    float sall = 0.f;
#pragma unroll
    for (int i = 0; i < 8; i++) sall += red[i][tx];
    float invS = 1.0f / sall;

    // pass 3: normalize + clip
    for (int p = ty; p < NP; p += 8) {
        size_t o = (size_t)p * NP + q;
        Gb[o] = fmaxf(Gb[o] * invS, 1e-8f);
    }
}

// ---------------- col2im (transposed-conv scatter as gather) + /4 --------
__global__ void k_col2im()
{
    int idx = blockIdx.x * 256 + threadIdx.x;
    if (idx >= B_ * C_ * H_ * W_) return;
    int ox = idx & 127, oy = (idx >> 7) & 127, c = (idx >> 14) & 63, b = idx >> 20;
    const float* Ub = g_U + (size_t)b * JB * NP;
    float r = 0.f;
    int ky0 = (oy + 1) & 1, kx0 = (ox + 1) & 1;
#pragma unroll
    for (int a = 0; a < 2; a++) {
        int ky = ky0 + 2 * a;
        int y = (oy + 1 - ky) >> 1;
        if ((unsigned)y < 64u) {
#pragma unroll
            for (int e = 0; e < 2; e++) {
                int kx = kx0 + 2 * e;
                int xx = (ox + 1 - kx) >> 1;
                if ((unsigned)xx < 64u)
                    r += Ub[(size_t)(c * 16 + ky * 4 + kx) * NP + y * 64 + xx];
            }
        }
    }
    g_x[idx] = 0.25f * r;
}

// ---------------- msfa im2col (dilated 3x3, pad=d) ------------------------
__global__ void k_im2col(int d)
{
    size_t idx = (size_t)blockIdx.x * 256 + threadIdx.x;
    if (idx >= (size_t)KC * MC) return;
    int m = (int)(idx & 65535);
    int k = (int)(idx >> 16);
    int xx = m & 127, y = (m >> 7) & 127, b = m >> 14;
    int kx = k % 3, ky = (k / 3) % 3, c = k / 9;
    int sy = y + (ky - 1) * d, sx = xx + (kx - 1) * d;
    float v = 0.f;
    if ((unsigned)sy < 128u && (unsigned)sx < 128u)
        v = g_x[(((size_t)b * 64 + c) * 128 + sy) * 128 + sx];
    g_Xcol[idx] = v;
}

// ---------------- repack conv weights (64,576) -> WT[k*64+n] -------------
__global__ void k_repack(const float* __restrict__ w)
{
    int idx = blockIdx.x * 256 + threadIdx.x;
    if (idx >= KC * C_) return;
    int n = idx & 63, k = idx >> 6;
    g_WT[idx] = w[n * KC + k];
}

// ---------------- wc2 1x1 conv + relu + softmax(4) ------------------------
__global__ void k_wc2_softmax(const float* __restrict__ w, const float* __restrict__ bias)
{
    __shared__ float sw[256];
    __shared__ float sb[4];
    int t = threadIdx.x;
    if (t < 256) sw[t] = w[t];
    if (t < 4)   sb[t] = bias[t];
    __syncthreads();
    int m = blockIdx.x * 256 + t;
    const float* hr = g_h + (size_t)m * 64;
    float a0 = sb[0], a1 = sb[1], a2 = sb[2], a3 = sb[3];
#pragma unroll 4
    for (int c = 0; c < 64; c++) {
        float hv = hr[c];
        a0 = fmaf(sw[c], hv, a0);
        a1 = fmaf(sw[64 + c], hv, a1);
        a2 = fmaf(sw[128 + c], hv, a2);
        a3 = fmaf(sw[192 + c], hv, a3);
    }
    a0 = fmaxf(a0, 0.f); a1 = fmaxf(a1, 0.f); a2 = fmaxf(a2, 0.f); a3 = fmaxf(a3, 0.f);
    float mx = fmaxf(fmaxf(a0, a1), fmaxf(a2, a3));
    float e0 = __expf(a0 - mx), e1 = __expf(a1 - mx), e2 = __expf(a2 - mx), e3 = __expf(a3 - mx);
    float r = 1.0f / (e0 + e1 + e2 + e3);
    g_wmap[(size_t)m * 4 + 0] = e0 * r;
    g_wmap[(size_t)m * 4 + 1] = e1 * r;
    g_wmap[(size_t)m * 4 + 2] = e2 * r;
    g_wmap[(size_t)m * 4 + 3] = e3 * r;
}

// ---------------- final transpose (m,c) -> NCHW ---------------------------
__global__ void k_transpose_out(float* __restrict__ out)  // grid (512,2,4), block (32,8)
{
    __shared__ float tile[32][33];
    int b = blockIdx.z;
    int c0 = blockIdx.y * 32;
    int m0 = blockIdx.x * 32;
    int tx = threadIdx.x, ty = threadIdx.y;
#pragma unroll
    for (int i = 0; i < 4; i++) {
        int mm = m0 + ty + i * 8;
        tile[ty + i * 8][tx] = g_acc[((size_t)b * 16384 + mm) * 64 + c0 + tx];
    }
    __syncthreads();
#pragma unroll
    for (int i = 0; i < 4; i++) {
        int cc = c0 + ty + i * 8;
        out[((size_t)b * 64 + cc) * 16384 + m0 + tx] = tile[tx][ty + i * 8];
    }
}

// ---------------- launch -----------------------------------------------
extern "C" void kernel_launch(void* const* d_in, const int* /*in_sizes*/, int /*n_in*/,
                              void* d_out, int /*out_size*/)
{
    const float* bg    = (const float*)d_in[0];
    const float* fg    = (const float*)d_in[1];
    const float* dil_w = (const float*)d_in[2];   // (4,64,64,3,3)
    const float* dil_b = (const float*)d_in[3];   // (4,64)
    const float* wc1_w = (const float*)d_in[4];   // (64,64,3,3)
    const float* wc1_b = (const float*)d_in[5];   // (64)
    const float* wc2_w = (const float*)d_in[6];   // (4,64,1,1)
    const float* wc2_b = (const float*)d_in[7];   // (4)
    float* out = (float*)d_out;

    float *pP, *pG, *pBg, *pU, *pXcol, *pWT, *pH, *pAcc, *pWmap;
    cudaGetSymbolAddress((void**)&pP,    g_P);
    cudaGetSymbolAddress((void**)&pG,    g_G);
    cudaGetSymbolAddress((void**)&pBg,   g_Bg);
    cudaGetSymbolAddress((void**)&pU,    g_U);
    cudaGetSymbolAddress((void**)&pXcol, g_Xcol);
    cudaGetSymbolAddress((void**)&pWT,   g_WT);
    cudaGetSymbolAddress((void**)&pH,    g_h);
    cudaGetSymbolAddress((void**)&pAcc,  g_acc);
    cudaGetSymbolAddress((void**)&pWmap, g_wmap);

    // ---- RAL ----
    k_resize<<<(B_ * C_ * HS * HS + 255) / 256, 256>>>(fg);
    k_build_P<<<(int)(((size_t)B_ * KP * NP + 255) / 256), 256>>>();

    // G = P^T P  (batched 4096x4096x576)
    k_gemm<128, 128, 16, 8, 8><<<dim3(NP / 128, NP / 128, B_), 256>>>(
        pP, pP, pG, KP, NP, NP, NP,
        (size_t)KP * NP, (size_t)KP * NP, (size_t)NP * NP,
        0, nullptr, nullptr, 0, 0);

    k_norms<<<(B_ * NP + 255) / 256, 256>>>();
    k_softmax<<<dim3(NP / 32, 1, B_), dim3(32, 8)>>>();

    k_build_Bg<<<(int)(((size_t)B_ * NP * JB + 255) / 256), 256>>>(bg);

    // U[j,q] = sum_p Bg[p,j] * attn[p,q]   (batched 1024x4096x4096)
    k_gemm<128, 128, 16, 8, 8><<<dim3(NP / 128, JB / 128, B_), 256>>>(
        pBg, pG, pU, NP, JB, NP, NP,
        (size_t)NP * JB, (size_t)NP * NP, (size_t)JB * NP,
        0, nullptr, nullptr, 0, 0);

    k_col2im<<<(B_ * C_ * H_ * W_ + 255) / 256, 256>>>();

    // ---- MSFA ----
    // d=1 im2col serves BOTH wc1 conv and dilation-1 branch
    k_im2col<<<(int)(((size_t)KC * MC + 255) / 256), 256>>>(1);

    // h = relu(conv3x3(x, wc1) + b)
    k_repack<<<(KC * C_ + 255) / 256, 256>>>(wc1_w);
    k_gemm<128, 64, 16, 8, 4><<<dim3(1, MC / 128, 1), 256>>>(
        pXcol, pWT, pH, KC, MC, C_, C_,
        0, 0, 0, 1, wc1_b, nullptr, 0, 0);

    // wmap = softmax(relu(1x1(h)))
    k_wc2_softmax<<<MC / 256, 256>>>(wc2_w, wc2_b);

    // dilated branches: acc (+)= wmap[:,i] * relu(conv_d(x) + b_i)
    for (int i = 0; i < 4; i++) {
        int d = 1 << i;
        if (i > 0)
            k_im2col<<<(int)(((size_t)KC * MC + 255) / 256), 256>>>(d);
        k_repack<<<(KC * C_ + 255) / 256, 256>>>(dil_w + (size_t)i * KC * C_);
        k_gemm<128, 64, 16, 8, 4><<<dim3(1, MC / 128, 1), 256>>>(
            pXcol, pWT, pAcc, KC, MC, C_, C_,
            0, 0, 0, 2, dil_b + i * C_, pWmap, i, (i > 0) ? 1 : 0);
    }

    k_transpose_out<<<dim3(16384 / 32, 2, B_), dim3(32, 8)>>>(out);
}

// round 3
// speedup vs baseline: 2.1445x; 2.1445x over previous
#include <cuda_runtime.h>
#include <cuda_bf16.h>
#include <cstddef>
#include <cstdint>

// ---------------- problem dims ----------------
#define B_  4
#define C_  64
#define H_  128
#define W_  128
#define HS  64            // fg half-size
#define NP  4096          // 64*64 patches / positions
#define KP  576           // 64ch * 3*3
#define JB  1024          // 64ch * 4*4 (bg patch columns)
#define MC  65536         // msfa positions: 4*128*128
#define KC  576           // msfa conv K

// ================= base-ISA helpers (NO arch-specific instructions) =======
__device__ __forceinline__ uint32_t smem_to_u32(const void* smem_ptr) {
    uint32_t addr;
    asm("{ .reg .u64 tmp; cvta.to.shared.u64 tmp, %1; cvt.u32.u64 %0, tmp; }"
        : "=r"(addr) : "l"(smem_ptr));
    return addr;
}
__device__ __forceinline__ void cp16(uint32_t dst, const void* src) {
    asm volatile("cp.async.cg.shared.global [%0], [%1], 16;"
                 :: "r"(dst), "l"(src));
}
#define CP_COMMIT() asm volatile("cp.async.commit_group;" ::: "memory")
#define CP_WAIT(n)  asm volatile("cp.async.wait_group %0;" :: "n"(n) : "memory")

__device__ __forceinline__ void ldsm4(uint32_t& a, uint32_t& b, uint32_t& c, uint32_t& d,
                                      uint32_t addr) {
    asm volatile("ldmatrix.sync.aligned.m8n8.x4.shared.b16 {%0,%1,%2,%3}, [%4];"
                 : "=r"(a), "=r"(b), "=r"(c), "=r"(d) : "r"(addr));
}
__device__ __forceinline__ void mma16816(float* c, const uint32_t* a, const uint32_t* b) {
    asm volatile(
        "mma.sync.aligned.m16n8k16.row.col.f32.bf16.bf16.f32 "
        "{%0,%1,%2,%3}, {%4,%5,%6,%7}, {%8,%9}, {%0,%1,%2,%3};"
        : "+f"(c[0]), "+f"(c[1]), "+f"(c[2]), "+f"(c[3])
        : "r"(a[0]), "r"(a[1]), "r"(a[2]), "r"(a[3]), "r"(b[0]), "r"(b[1]));
}

// ---------------- scratch (static device globals; no allocation) ----------
static __device__ __align__(16) float g_fgs[(size_t)B_ * C_ * HS * HS];
static __device__ __align__(16) __nv_bfloat16 g_Pth[(size_t)B_ * NP * KP];
static __device__ __align__(16) __nv_bfloat16 g_Ptl[(size_t)B_ * NP * KP];
static __device__ __align__(16) float g_S[(size_t)B_ * NP * NP];           // Gram, row-major [q][p]
static __device__ __align__(16) float g_inv[B_ * NP];
static __device__ __align__(16) __nv_bfloat16 g_ATh[(size_t)B_ * NP * NP]; // attnT [q][p]
static __device__ __align__(16) __nv_bfloat16 g_ATl[(size_t)B_ * NP * NP];
static __device__ __align__(16) __nv_bfloat16 g_Bgth[(size_t)B_ * JB * NP];
static __device__ __align__(16) __nv_bfloat16 g_Bgtl[(size_t)B_ * JB * NP];
static __device__ __align__(16) float g_U[(size_t)B_ * JB * NP];           // [b][j][q]
static __device__ __align__(16) float g_x[(size_t)B_ * C_ * H_ * W_];
static __device__ __align__(16) __nv_bfloat16 g_Xh[(size_t)MC * KC];       // q-major im2col
static __device__ __align__(16) __nv_bfloat16 g_Xl[(size_t)MC * KC];
static __device__ __align__(16) __nv_bfloat16 g_Wh[C_ * KC];
static __device__ __align__(16) __nv_bfloat16 g_Wl[C_ * KC];
static __device__ __align__(16) float g_h[(size_t)MC * C_];
static __device__ __align__(16) float g_wmap[(size_t)MC * 4];
static __device__ __align__(16) float g_acc[(size_t)MC * C_];

__device__ __forceinline__ void split2(float v, __nv_bfloat16& h, __nv_bfloat16& l)
{
    h = __float2bfloat16(v);
    l = __float2bfloat16(v - __bfloat162float(h));
}

// ---------------- bilinear half-resize (align_corners) --------------------
__global__ void k_resize(const float* __restrict__ fg)
{
    int idx = blockIdx.x * 256 + threadIdx.x;
    if (idx >= B_ * C_ * HS * HS) return;
    int x = idx & 63, y = (idx >> 6) & 63;
    int bc = idx >> 12;
    const float* src = fg + (size_t)bc * H_ * W_;
    float cy = (float)y * (127.0f / 63.0f);
    float cx = (float)x * (127.0f / 63.0f);
    int iy = (int)cy; if (iy > 127) iy = 127;
    int ix = (int)cx; if (ix > 127) ix = 127;
    int iy1 = min(iy + 1, 127), ix1 = min(ix + 1, 127);
    float wy = cy - (float)iy, wx = cx - (float)ix;
    float v00 = src[iy * 128 + ix],  v01 = src[iy * 128 + ix1];
    float v10 = src[iy1 * 128 + ix], v11 = src[iy1 * 128 + ix1];
    g_fgs[idx] = (1.f - wy) * ((1.f - wx) * v00 + wx * v01)
               +        wy  * ((1.f - wx) * v10 + wx * v11);
}

// ---------------- fg im2col (q-major, split bf16): Pt[b][q][k] ------------
__global__ void k_build_Pt()
{
    size_t idx = (size_t)blockIdx.x * 256 + threadIdx.x;
    if (idx >= (size_t)B_ * NP * KP) return;
    int k = (int)(idx % KP);
    size_t t = idx / KP;
    int q = (int)(t & (NP - 1));
    int b = (int)(t >> 12);
    int x = q & 63, y = q >> 6;
    int dx = k % 3, dy = (k / 3) % 3, c = k / 9;
    int sy = y + dy - 1, sx = x + dx - 1;
    float v = 0.f;
    if ((unsigned)sy < 64u && (unsigned)sx < 64u)
        v = g_fgs[((size_t)(b * C_ + c) << 12) + sy * 64 + sx];
    split2(v, g_Pth[idx], g_Ptl[idx]);
}

// ---------------- bg im2col (j-major, split bf16): Bgt[b][j][p] -----------
__global__ void k_build_Bgt(const float* __restrict__ bg)
{
    size_t idx = (size_t)blockIdx.x * 256 + threadIdx.x;
    if (idx >= (size_t)B_ * JB * NP) return;
    int p = (int)(idx & 4095);
    int j = (int)((idx >> 12) & 1023);
    int b = (int)(idx >> 22);
    int c = j >> 4, ky = (j >> 2) & 3, kx = j & 3;
    int py = p >> 6, px = p & 63;
    int sy = 2 * py + ky - 1, sx = 2 * px + kx - 1;
    float v = 0.f;
    if ((unsigned)sy < 128u && (unsigned)sx < 128u)
        v = bg[(((size_t)b * 64 + c) * 128 + sy) * 128 + sx];
    split2(v, g_Bgth[idx], g_Bgtl[idx]);
}

// ================= split-bf16 warp-MMA GEMM (mma.sync, base ISA) ==========
// C[m][n] = sum_k A[m][k]*B[n][k]; A,B bf16 hi/lo pairs, K-major rows.
// EPI: 0 = store; 1 = relu(v+bias[n]); 2 = (+)= wmap[m*4+wsel]*relu(v+bias[n])
template<int BM, int BN, int EPI>
__global__ void __launch_bounds__(32 * (BM / 64) * (BN / 32))
k_hgemm(const __nv_bfloat16* __restrict__ Ah, const __nv_bfloat16* __restrict__ Al,
        const __nv_bfloat16* __restrict__ Bh, const __nv_bfloat16* __restrict__ Bl,
        float* __restrict__ C, int K, int lda, int ldb, int ldc,
        size_t sA, size_t sB, size_t sC,
        const float* __restrict__ bias, const float* __restrict__ wmap,
        int wsel, int accum)
{
    constexpr int NWN = BN / 32;
    constexpr int T   = 32 * (BM / 64) * NWN;
    constexpr int AT  = BM * 80;          // bytes per A tile (stride 40 halves)
    constexpr int BT  = BN * 80;
    constexpr int STAGE = 2 * AT + 2 * BT;
    constexpr int CA = BM * 4, CB = BN * 4;     // 16B chunks per tile
    constexpr int TC = 2 * (CA + CB);

    extern __shared__ char sm[];
    uint32_t sb = smem_to_u32(sm);

    Ah += blockIdx.z * sA; Al += blockIdx.z * sA;
    Bh += blockIdx.z * sB; Bl += blockIdx.z * sB;
    C  += blockIdx.z * sC;
    const int m0 = blockIdx.y * BM, n0 = blockIdx.x * BN;

    const int tid  = threadIdx.x;
    const int warp = tid >> 5, ln = tid & 31;
    const int wm = (warp / NWN) * 64;
    const int wn = (warp % NWN) * 32;

    float acc[4][4][4];
#pragma unroll
    for (int i = 0; i < 4; i++)
#pragma unroll
        for (int j = 0; j < 4; j++)
#pragma unroll
            for (int r = 0; r < 4; r++) acc[i][j][r] = 0.f;

    auto load_stage = [&](int s, int kt) {
        uint32_t base = sb + s * STAGE;
#pragma unroll
        for (int i = 0; i < TC / T; i++) {
            int idx = tid + i * T;
            int r, kg;
            uint32_t dsm;
            const __nv_bfloat16* g;
            if (idx < CA) {
                r = idx >> 2; kg = idx & 3;
                dsm = base + r * 80 + kg * 16;
                g = Ah + (size_t)(m0 + r) * lda + kt + kg * 8;
            } else if (idx < 2 * CA) {
                int u = idx - CA; r = u >> 2; kg = u & 3;
                dsm = base + AT + r * 80 + kg * 16;
                g = Al + (size_t)(m0 + r) * lda + kt + kg * 8;
            } else if (idx < 2 * CA + CB) {
                int u = idx - 2 * CA; r = u >> 2; kg = u & 3;
                dsm = base + 2 * AT + r * 80 + kg * 16;
                g = Bh + (size_t)(n0 + r) * ldb + kt + kg * 8;
            } else {
                int u = idx - 2 * CA - CB; r = u >> 2; kg = u & 3;
                dsm = base + 2 * AT + BT + r * 80 + kg * 16;
                g = Bl + (size_t)(n0 + r) * ldb + kt + kg * 8;
            }
            cp16(dsm, g);
        }
    };

    // lane-invariant fragment address offsets (padded stride: conflict-free)
    const uint32_t aoff = (uint32_t)((wm + ((ln >> 3) & 1) * 8 + (ln & 7)) * 80
                                     + ((ln >> 4) * 8) * 2);
    const uint32_t boff = (uint32_t)((wn + (ln >> 4) * 8 + (ln & 7)) * 80
                                     + (((ln >> 3) & 1) * 8) * 2);

    const int nc = K >> 5;
    load_stage(0, 0);
    CP_COMMIT();

    for (int c = 0; c < nc; c++) {
        if (c + 1 < nc) {
            load_stage((c + 1) & 1, (c + 1) << 5);
            CP_COMMIT();
            CP_WAIT(1);
        } else {
            CP_WAIT(0);
        }
        __syncthreads();

        uint32_t stg = sb + (c & 1) * STAGE;
        uint32_t aH = stg, aL = stg + AT, bH = stg + 2 * AT, bL = stg + 2 * AT + BT;

#pragma unroll
        for (int ks = 0; ks < 2; ks++) {
            uint32_t ah[4][4], al[4][4], bh[4][2], bl[4][2];
#pragma unroll
            for (int mt = 0; mt < 4; mt++)
                ldsm4(ah[mt][0], ah[mt][1], ah[mt][2], ah[mt][3],
                      aH + aoff + mt * 1280 + ks * 32);
#pragma unroll
            for (int mt = 0; mt < 4; mt++)
                ldsm4(al[mt][0], al[mt][1], al[mt][2], al[mt][3],
                      aL + aoff + mt * 1280 + ks * 32);
#pragma unroll
            for (int j = 0; j < 2; j++)
                ldsm4(bh[j * 2][0], bh[j * 2][1], bh[j * 2 + 1][0], bh[j * 2 + 1][1],
                      bH + boff + j * 1280 + ks * 32);
#pragma unroll
            for (int j = 0; j < 2; j++)
                ldsm4(bl[j * 2][0], bl[j * 2][1], bl[j * 2 + 1][0], bl[j * 2 + 1][1],
                      bL + boff + j * 1280 + ks * 32);
#pragma unroll
            for (int mt = 0; mt < 4; mt++)
#pragma unroll
                for (int nt = 0; nt < 4; nt++) {
                    mma16816(acc[mt][nt], ah[mt], bh[nt]);
                    mma16816(acc[mt][nt], ah[mt], bl[nt]);
                    mma16816(acc[mt][nt], al[mt], bh[nt]);
                }
        }
        __syncthreads();
    }

    // ---- epilogue: fragments -> gmem ----
    const int g = ln >> 2, t = ln & 3;
#pragma unroll
    for (int mt = 0; mt < 4; mt++) {
#pragma unroll
        for (int nt = 0; nt < 4; nt++) {
            int m = m0 + wm + mt * 16 + g;
            int n = n0 + wn + nt * 8 + t * 2;
#pragma unroll
            for (int half = 0; half < 2; half++) {
                int mm = m + half * 8;
                float v0 = acc[mt][nt][half * 2 + 0];
                float v1 = acc[mt][nt][half * 2 + 1];
                size_t o = (size_t)mm * ldc + n;
                if (EPI == 0) {
                    C[o] = v0; C[o + 1] = v1;
                } else if (EPI == 1) {
                    C[o]     = fmaxf(v0 + bias[n], 0.f);
                    C[o + 1] = fmaxf(v1 + bias[n + 1], 0.f);
                } else {
                    float w = wmap[(size_t)mm * 4 + wsel];
                    float w0 = w * fmaxf(v0 + bias[n], 0.f);
                    float w1 = w * fmaxf(v1 + bias[n + 1], 0.f);
                    if (accum) { C[o] += w0; C[o + 1] += w1; }
                    else       { C[o]  = w0; C[o + 1]  = w1; }
                }
            }
        }
    }
}

// ---------------- norms from diag(S) --------------------------------------
__global__ void k_norms()
{
    int idx = blockIdx.x * 256 + threadIdx.x;
    if (idx >= B_ * NP) return;
    int b = idx >> 12, q = idx & (NP - 1);
    float d = g_S[((size_t)b * NP + q) * NP + q];
    float n = sqrtf(fmaxf(d, 0.f));
    g_inv[idx] = 1.0f / fmaxf(n, 1e-4f);
}

// ---------------- row softmax on S -> attnT (bf16 hi/lo) ------------------
__global__ void __launch_bounds__(256) k_softmax_rows()
{
    __shared__ float red[8];
    const int q = blockIdx.x & (NP - 1);
    const int b = blockIdx.x >> 12;
    const size_t base = ((size_t)b * NP + q) * NP;
    const float* invb = g_inv + b * NP;
    const int tid = threadIdx.x, lid = tid & 31, wid = tid >> 5;

    float v[16];
    float m = -3e38f;
#pragma unroll
    for (int i = 0; i < 16; i++) {
        int p = tid + i * 256;
        v[i] = invb[p] * g_S[base + p];
        m = fmaxf(m, v[i]);
    }
#pragma unroll
    for (int o = 16; o; o >>= 1) m = fmaxf(m, __shfl_xor_sync(~0u, m, o));
    if (lid == 0) red[wid] = m;
    __syncthreads();
    float mall = red[0];
#pragma unroll
    for (int i = 1; i < 8; i++) mall = fmaxf(mall, red[i]);
    __syncthreads();

    float s = 0.f;
#pragma unroll
    for (int i = 0; i < 16; i++) { v[i] = __expf(10.f * (v[i] - mall)); s += v[i]; }
#pragma unroll
    for (int o = 16; o; o >>= 1) s += __shfl_xor_sync(~0u, s, o);
    if (lid == 0) red[wid] = s;
    __syncthreads();
    float sall = 0.f;
#pragma unroll
    for (int i = 0; i < 8; i++) sall += red[i];
    float invS = 1.0f / sall;
#pragma unroll
    for (int i = 0; i < 16; i++) {
        int p = tid + i * 256;
        float val = fmaxf(v[i] * invS, 1e-8f);
        __nv_bfloat16 h, l;
        split2(val, h, l);
        g_ATh[base + p] = h;
        g_ATl[base + p] = l;
    }
}

// ---------------- col2im (transposed-conv gather) + /4 --------------------
__global__ void k_col2im()
{
    int idx = blockIdx.x * 256 + threadIdx.x;
    if (idx >= B_ * C_ * H_ * W_) return;
    int ox = idx & 127, oy = (idx >> 7) & 127, c = (idx >> 14) & 63, b = idx >> 20;
    const float* Ub = g_U + (size_t)b * JB * NP;
    float r = 0.f;
    int ky0 = (oy + 1) & 1, kx0 = (ox + 1) & 1;
#pragma unroll
    for (int a = 0; a < 2; a++) {
        int ky = ky0 + 2 * a;
        int y = (oy + 1 - ky) >> 1;
        if ((unsigned)y < 64u) {
#pragma unroll
            for (int e = 0; e < 2; e++) {
                int kx = kx0 + 2 * e;
                int xx = (ox + 1 - kx) >> 1;
                if ((unsigned)xx < 64u)
                    r += Ub[(size_t)(c * 16 + ky * 4 + kx) * NP + y * 64 + xx];
            }
        }
    }
    g_x[idx] = 0.25f * r;
}

// ---------------- msfa im2col (q-major, split bf16) -----------------------
__global__ void k_im2col_t(int d)
{
    size_t idx = (size_t)blockIdx.x * 256 + threadIdx.x;
    if (idx >= (size_t)MC * KC) return;
    int k = (int)(idx % KC);
    int m = (int)(idx / KC);
    int xx = m & 127, y = (m >> 7) & 127, b = m >> 14;
    int kx = k % 3, ky = (k / 3) % 3, c = k / 9;
    int sy = y + (ky - 1) * d, sx = xx + (kx - 1) * d;
    float v = 0.f;
    if ((unsigned)sy < 128u && (unsigned)sx < 128u)
        v = g_x[(((size_t)b * 64 + c) * 128 + sy) * 128 + sx];
    split2(v, g_Xh[idx], g_Xl[idx]);
}

// ---------------- weight split (64 x 576, n-major K-major) ----------------
__global__ void k_wsplit(const float* __restrict__ w)
{
    int idx = blockIdx.x * 256 + threadIdx.x;
    if (idx >= C_ * KC) return;
    split2(w[idx], g_Wh[idx], g_Wl[idx]);
}

// ---------------- wc2 1x1 conv + relu + softmax(4) ------------------------
__global__ void k_wc2_softmax(const float* __restrict__ w, const float* __restrict__ bias)
{
    __shared__ float sw[256];
    __shared__ float sb[4];
    int t = threadIdx.x;
    if (t < 256) sw[t] = w[t];
    if (t < 4)   sb[t] = bias[t];
    __syncthreads();
    int m = blockIdx.x * 256 + t;
    const float* hr = g_h + (size_t)m * 64;
    float a0 = sb[0], a1 = sb[1], a2 = sb[2], a3 = sb[3];
#pragma unroll 4
    for (int c = 0; c < 64; c++) {
        float hv = hr[c];
        a0 = fmaf(sw[c], hv, a0);
        a1 = fmaf(sw[64 + c], hv, a1);
        a2 = fmaf(sw[128 + c], hv, a2);
        a3 = fmaf(sw[192 + c], hv, a3);
    }
    a0 = fmaxf(a0, 0.f); a1 = fmaxf(a1, 0.f); a2 = fmaxf(a2, 0.f); a3 = fmaxf(a3, 0.f);
    float mx = fmaxf(fmaxf(a0, a1), fmaxf(a2, a3));
    float e0 = __expf(a0 - mx), e1 = __expf(a1 - mx), e2 = __expf(a2 - mx), e3 = __expf(a3 - mx);
    float r = 1.0f / (e0 + e1 + e2 + e3);
    g_wmap[(size_t)m * 4 + 0] = e0 * r;
    g_wmap[(size_t)m * 4 + 1] = e1 * r;
    g_wmap[(size_t)m * 4 + 2] = e2 * r;
    g_wmap[(size_t)m * 4 + 3] = e3 * r;
}

// ---------------- final transpose (m,c) -> NCHW ---------------------------
__global__ void k_transpose_out(float* __restrict__ out)
{
    __shared__ float tile[32][33];
    int b = blockIdx.z;
    int c0 = blockIdx.y * 32;
    int m0 = blockIdx.x * 32;
    int tx = threadIdx.x, ty = threadIdx.y;
#pragma unroll
    for (int i = 0; i < 4; i++) {
        int mm = m0 + ty + i * 8;
        tile[ty + i * 8][tx] = g_acc[((size_t)b * 16384 + mm) * 64 + c0 + tx];
    }
    __syncthreads();
#pragma unroll
    for (int i = 0; i < 4; i++) {
        int cc = c0 + ty + i * 8;
        out[((size_t)b * 64 + cc) * 16384 + m0 + tx] = tile[tx][ty + i * 8];
    }
}

// ---------------- launch ---------------------------------------------------
extern "C" void kernel_launch(void* const* d_in, const int* /*in_sizes*/, int /*n_in*/,
                              void* d_out, int /*out_size*/)
{
    const float* bg    = (const float*)d_in[0];
    const float* fg    = (const float*)d_in[1];
    const float* dil_w = (const float*)d_in[2];
    const float* dil_b = (const float*)d_in[3];
    const float* wc1_w = (const float*)d_in[4];
    const float* wc1_b = (const float*)d_in[5];
    const float* wc2_w = (const float*)d_in[6];
    const float* wc2_b = (const float*)d_in[7];
    float* out = (float*)d_out;

    __nv_bfloat16 *pPth, *pPtl, *pATh, *pATl, *pBgth, *pBgtl, *pXh, *pXl, *pWh, *pWl;
    float *pS, *pU, *pH, *pAcc, *pWmap;
    cudaGetSymbolAddress((void**)&pPth,  g_Pth);
    cudaGetSymbolAddress((void**)&pPtl,  g_Ptl);
    cudaGetSymbolAddress((void**)&pS,    g_S);
    cudaGetSymbolAddress((void**)&pATh,  g_ATh);
    cudaGetSymbolAddress((void**)&pATl,  g_ATl);
    cudaGetSymbolAddress((void**)&pBgth, g_Bgth);
    cudaGetSymbolAddress((void**)&pBgtl, g_Bgtl);
    cudaGetSymbolAddress((void**)&pU,    g_U);
    cudaGetSymbolAddress((void**)&pXh,   g_Xh);
    cudaGetSymbolAddress((void**)&pXl,   g_Xl);
    cudaGetSymbolAddress((void**)&pWh,   g_Wh);
    cudaGetSymbolAddress((void**)&pWl,   g_Wl);
    cudaGetSymbolAddress((void**)&pH,    g_h);
    cudaGetSymbolAddress((void**)&pAcc,  g_acc);
    cudaGetSymbolAddress((void**)&pWmap, g_wmap);

    // dynamic smem: 2 stages * (2*BM + 2*BN) rows * 80B
    const int SM128 = 2 * (2 * 128 * 80 + 2 * 128 * 80);   // 81920
    const int SM64  = 2 * (2 * 128 * 80 + 2 * 64 * 80);    // 61440
    cudaFuncSetAttribute(k_hgemm<128, 128, 0>, cudaFuncAttributeMaxDynamicSharedMemorySize, SM128);
    cudaFuncSetAttribute(k_hgemm<128, 64, 1>,  cudaFuncAttributeMaxDynamicSharedMemorySize, SM64);
    cudaFuncSetAttribute(k_hgemm<128, 64, 2>,  cudaFuncAttributeMaxDynamicSharedMemorySize, SM64);

    // ---- RAL ----
    k_resize<<<(B_ * C_ * HS * HS + 255) / 256, 256>>>(fg);
    k_build_Pt<<<(int)(((size_t)B_ * NP * KP + 255) / 256), 256>>>();

    // S = Pt * Pt^T (Gram), row-major [q][p]; K = 576
    k_hgemm<128, 128, 0><<<dim3(NP / 128, NP / 128, B_), 256, SM128>>>(
        pPth, pPtl, pPth, pPtl, pS, KP, KP, KP, NP,
        (size_t)NP * KP, (size_t)NP * KP, (size_t)NP * NP,
        nullptr, nullptr, 0, 0);

    k_norms<<<(B_ * NP + 255) / 256, 256>>>();
    k_softmax_rows<<<B_ * NP, 256>>>();

    k_build_Bgt<<<(int)(((size_t)B_ * JB * NP + 255) / 256), 256>>>(bg);

    // U[j][q] = sum_p Bgt[j][p] * attnT[q][p]; K = 4096
    k_hgemm<128, 128, 0><<<dim3(NP / 128, JB / 128, B_), 256, SM128>>>(
        pBgth, pBgtl, pATh, pATl, pU, NP, NP, NP, NP,
        (size_t)JB * NP, (size_t)NP * NP, (size_t)JB * NP,
        nullptr, nullptr, 0, 0);

    k_col2im<<<(B_ * C_ * H_ * W_ + 255) / 256, 256>>>();

    // ---- MSFA ----
    k_im2col_t<<<(int)(((size_t)MC * KC + 255) / 256), 256>>>(1);
    k_wsplit<<<(C_ * KC + 255) / 256, 256>>>(wc1_w);
    k_hgemm<128, 64, 1><<<dim3(1, MC / 128, 1), 128, SM64>>>(
        pXh, pXl, pWh, pWl, pH, KC, KC, KC, C_,
        0, 0, 0, wc1_b, nullptr, 0, 0);

    k_wc2_softmax<<<MC / 256, 256>>>(wc2_w, wc2_b);

    for (int i = 0; i < 4; i++) {
        int d = 1 << i;
        if (i > 0)
            k_im2col_t<<<(int)(((size_t)MC * KC + 255) / 256), 256>>>(d);
        k_wsplit<<<(C_ * KC + 255) / 256, 256>>>(dil_w + (size_t)i * KC * C_);
        k_hgemm<128, 64, 2><<<dim3(1, MC / 128, 1), 128, SM64>>>(
            pXh, pXl, pWh, pWl, pAcc, KC, KC, KC, C_,
            0, 0, 0, dil_b + i * C_, pWmap, i, (i > 0) ? 1 : 0);
    }

    k_transpose_out<<<dim3(16384 / 32, 2, B_), dim3(32, 8)>>>(out);
}

// round 4
// speedup vs baseline: 2.9120x; 1.3579x over previous
#include <cuda_runtime.h>
#include <cuda_bf16.h>
#include <cstddef>
#include <cstdint>

// ---------------- problem dims ----------------
#define B_  4
#define C_  64
#define H_  128
#define W_  128
#define HS  64            // fg half-size
#define NP  4096          // 64*64 patches / positions
#define KP  576           // 64ch * 3*3
#define JB  1024          // 64ch * 4*4 (bg patch columns)
#define MC  65536         // msfa positions: 4*128*128
#define KC  576           // msfa conv K

// ================= base-ISA helpers =======================================
__device__ __forceinline__ uint32_t smem_to_u32(const void* smem_ptr) {
    uint32_t addr;
    asm("{ .reg .u64 tmp; cvta.to.shared.u64 tmp, %1; cvt.u32.u64 %0, tmp; }"
        : "=r"(addr) : "l"(smem_ptr));
    return addr;
}
__device__ __forceinline__ void cp16(uint32_t dst, const void* src) {
    asm volatile("cp.async.cg.shared.global [%0], [%1], 16;"
                 :: "r"(dst), "l"(src));
}
__device__ __forceinline__ void cp16z(uint32_t dst, const void* src, int sz) {
    asm volatile("cp.async.cg.shared.global [%0], [%1], 16, %2;"
                 :: "r"(dst), "l"(src), "r"(sz));
}
#define CP_COMMIT() asm volatile("cp.async.commit_group;" ::: "memory")
#define CP_WAIT(n)  asm volatile("cp.async.wait_group %0;" :: "n"(n) : "memory")

__device__ __forceinline__ void ldsm4(uint32_t& a, uint32_t& b, uint32_t& c, uint32_t& d,
                                      uint32_t addr) {
    asm volatile("ldmatrix.sync.aligned.m8n8.x4.shared.b16 {%0,%1,%2,%3}, [%4];"
                 : "=r"(a), "=r"(b), "=r"(c), "=r"(d) : "r"(addr));
}
__device__ __forceinline__ void mma16816(float* c, const uint32_t* a, const uint32_t* b) {
    asm volatile(
        "mma.sync.aligned.m16n8k16.row.col.f32.bf16.bf16.f32 "
        "{%0,%1,%2,%3}, {%4,%5,%6,%7}, {%8,%9}, {%0,%1,%2,%3};"
        : "+f"(c[0]), "+f"(c[1]), "+f"(c[2]), "+f"(c[3])
        : "r"(a[0]), "r"(a[1]), "r"(a[2]), "r"(a[3]), "r"(b[0]), "r"(b[1]));
}

// ---------------- scratch (static device globals; no allocation) ----------
static __device__ __align__(16) float g_fgs[(size_t)B_ * C_ * HS * HS];
static __device__ __align__(16) __nv_bfloat16 g_Pth[(size_t)B_ * NP * KP];
static __device__ __align__(16) __nv_bfloat16 g_Ptl[(size_t)B_ * NP * KP];
static __device__ __align__(16) float g_S[(size_t)B_ * NP * NP];           // Gram [q][p]
static __device__ __align__(16) float g_inv[B_ * NP];
static __device__ __align__(16) __nv_bfloat16 g_ATh[(size_t)B_ * NP * NP]; // attnT [q][p]
static __device__ __align__(16) __nv_bfloat16 g_ATl[(size_t)B_ * NP * NP];
static __device__ __align__(16) __nv_bfloat16 g_Bgth[(size_t)B_ * JB * NP];
static __device__ __align__(16) __nv_bfloat16 g_Bgtl[(size_t)B_ * JB * NP];
static __device__ __align__(16) float g_U[(size_t)B_ * JB * NP];           // [b][j][q]
static __device__ __align__(16) __nv_bfloat16 g_xh[(size_t)B_ * H_ * W_ * C_]; // NHWC hi
static __device__ __align__(16) __nv_bfloat16 g_xl[(size_t)B_ * H_ * W_ * C_]; // NHWC lo
static __device__ __align__(16) __nv_bfloat16 g_Wh[128 * KC];
static __device__ __align__(16) __nv_bfloat16 g_Wl[128 * KC];
static __device__ __align__(16) float g_h[(size_t)MC * C_];
static __device__ __align__(16) float g_wmap[(size_t)MC * 4];
static __device__ __align__(16) float g_acc[(size_t)MC * C_];

__device__ __forceinline__ void split2(float v, __nv_bfloat16& h, __nv_bfloat16& l)
{
    h = __float2bfloat16(v);
    l = __float2bfloat16(v - __bfloat162float(h));
}

// ---------------- bilinear half-resize (align_corners) --------------------
__global__ void k_resize(const float* __restrict__ fg)
{
    int idx = blockIdx.x * 256 + threadIdx.x;
    if (idx >= B_ * C_ * HS * HS) return;
    int x = idx & 63, y = (idx >> 6) & 63;
    int bc = idx >> 12;
    const float* src = fg + (size_t)bc * H_ * W_;
    float cy = (float)y * (127.0f / 63.0f);
    float cx = (float)x * (127.0f / 63.0f);
    int iy = (int)cy; if (iy > 127) iy = 127;
    int ix = (int)cx; if (ix > 127) ix = 127;
    int iy1 = min(iy + 1, 127), ix1 = min(ix + 1, 127);
    float wy = cy - (float)iy, wx = cx - (float)ix;
    float v00 = src[iy * 128 + ix],  v01 = src[iy * 128 + ix1];
    float v10 = src[iy1 * 128 + ix], v11 = src[iy1 * 128 + ix1];
    g_fgs[idx] = (1.f - wy) * ((1.f - wx) * v00 + wx * v01)
               +        wy  * ((1.f - wx) * v10 + wx * v11);
}

// ---------------- fg im2col (q-major, split bf16): Pt[b][q][k] ------------
__global__ void k_build_Pt()
{
    size_t idx = (size_t)blockIdx.x * 256 + threadIdx.x;
    if (idx >= (size_t)B_ * NP * KP) return;
    int k = (int)(idx % KP);
    size_t t = idx / KP;
    int q = (int)(t & (NP - 1));
    int b = (int)(t >> 12);
    int x = q & 63, y = q >> 6;
    int dx = k % 3, dy = (k / 3) % 3, c = k / 9;
    int sy = y + dy - 1, sx = x + dx - 1;
    float v = 0.f;
    if ((unsigned)sy < 64u && (unsigned)sx < 64u)
        v = g_fgs[((size_t)(b * C_ + c) << 12) + sy * 64 + sx];
    split2(v, g_Pth[idx], g_Ptl[idx]);
}

// ---------------- bg im2col (j-major, split bf16): Bgt[b][j][p] -----------
__global__ void k_build_Bgt(const float* __restrict__ bg)
{
    size_t idx = (size_t)blockIdx.x * 256 + threadIdx.x;
    if (idx >= (size_t)B_ * JB * NP) return;
    int p = (int)(idx & 4095);
    int j = (int)((idx >> 12) & 1023);
    int b = (int)(idx >> 22);
    int c = j >> 4, ky = (j >> 2) & 3, kx = j & 3;
    int py = p >> 6, px = p & 63;
    int sy = 2 * py + ky - 1, sx = 2 * px + kx - 1;
    float v = 0.f;
    if ((unsigned)sy < 128u && (unsigned)sx < 128u)
        v = bg[(((size_t)b * 64 + c) * 128 + sy) * 128 + sx];
    split2(v, g_Bgth[idx], g_Bgtl[idx]);
}

// ================= split-bf16 warp-MMA GEMM (mma.sync) ====================
// C[m][n] = sum_k A[m][k]*B[n][k]; A,B bf16 hi/lo pairs, K-major rows.
// SYM=1: grid.x enumerates upper-triangle 128x128 blocks; mirror-store.
template<int BM, int BN, int SYM>
__global__ void __launch_bounds__(32 * (BM / 64) * (BN / 32))
k_hgemm(const __nv_bfloat16* __restrict__ Ah, const __nv_bfloat16* __restrict__ Al,
        const __nv_bfloat16* __restrict__ Bh, const __nv_bfloat16* __restrict__ Bl,
        float* __restrict__ C, int K, int lda, int ldb, int ldc,
        size_t sA, size_t sB, size_t sC)
{
    constexpr int NWN = BN / 32;
    constexpr int T   = 32 * (BM / 64) * NWN;
    constexpr int AT  = BM * 80;
    constexpr int BT  = BN * 80;
    constexpr int STAGE = 2 * AT + 2 * BT;
    constexpr int CA = BM * 4, CB = BN * 4;
    constexpr int TC = 2 * (CA + CB);

    extern __shared__ char sm[];
    uint32_t sb = smem_to_u32(sm);

    Ah += blockIdx.z * sA; Al += blockIdx.z * sA;
    Bh += blockIdx.z * sB; Bl += blockIdx.z * sB;
    C  += blockIdx.z * sC;

    int m0, n0;
    if (SYM) {
        int tt = blockIdx.x, bi = 0, rl = ldc / BM;
        while (tt >= rl) { tt -= rl; rl--; bi++; }
        m0 = bi * BM;
        n0 = (bi + tt) * BN;
    } else {
        m0 = blockIdx.y * BM;
        n0 = blockIdx.x * BN;
    }

    const int tid  = threadIdx.x;
    const int warp = tid >> 5, ln = tid & 31;
    const int wm = (warp / NWN) * 64;
    const int wn = (warp % NWN) * 32;

    float acc[4][4][4];
#pragma unroll
    for (int i = 0; i < 4; i++)
#pragma unroll
        for (int j = 0; j < 4; j++)
#pragma unroll
            for (int r = 0; r < 4; r++) acc[i][j][r] = 0.f;

    auto load_stage = [&](int s, int kt) {
        uint32_t base = sb + s * STAGE;
#pragma unroll
        for (int i = 0; i < TC / T; i++) {
            int idx = tid + i * T;
            int r, kg;
            uint32_t dsm;
            const __nv_bfloat16* g;
            if (idx < CA) {
                r = idx >> 2; kg = idx & 3;
                dsm = base + r * 80 + kg * 16;
                g = Ah + (size_t)(m0 + r) * lda + kt + kg * 8;
            } else if (idx < 2 * CA) {
                int u = idx - CA; r = u >> 2; kg = u & 3;
                dsm = base + AT + r * 80 + kg * 16;
                g = Al + (size_t)(m0 + r) * lda + kt + kg * 8;
            } else if (idx < 2 * CA + CB) {
                int u = idx - 2 * CA; r = u >> 2; kg = u & 3;
                dsm = base + 2 * AT + r * 80 + kg * 16;
                g = Bh + (size_t)(n0 + r) * ldb + kt + kg * 8;
            } else {
                int u = idx - 2 * CA - CB; r = u >> 2; kg = u & 3;
                dsm = base + 2 * AT + BT + r * 80 + kg * 16;
                g = Bl + (size_t)(n0 + r) * ldb + kt + kg * 8;
            }
            cp16(dsm, g);
        }
    };

    const uint32_t aoff = (uint32_t)((wm + ((ln >> 3) & 1) * 8 + (ln & 7)) * 80
                                     + ((ln >> 4) * 8) * 2);
    const uint32_t boff = (uint32_t)((wn + (ln >> 4) * 8 + (ln & 7)) * 80
                                     + (((ln >> 3) & 1) * 8) * 2);

    const int nc = K >> 5;
    load_stage(0, 0);
    CP_COMMIT();

    for (int c = 0; c < nc; c++) {
        if (c + 1 < nc) {
            load_stage((c + 1) & 1, (c + 1) << 5);
            CP_COMMIT();
            CP_WAIT(1);
        } else {
            CP_WAIT(0);
        }
        __syncthreads();

        uint32_t stg = sb + (c & 1) * STAGE;
        uint32_t aH = stg, aL = stg + AT, bH = stg + 2 * AT, bL = stg + 2 * AT + BT;

#pragma unroll
        for (int ks = 0; ks < 2; ks++) {
            uint32_t ah[4][4], al[4][4], bh[4][2], bl[4][2];
#pragma unroll
            for (int mt = 0; mt < 4; mt++)
                ldsm4(ah[mt][0], ah[mt][1], ah[mt][2], ah[mt][3],
                      aH + aoff + mt * 1280 + ks * 32);
#pragma unroll
            for (int mt = 0; mt < 4; mt++)
                ldsm4(al[mt][0], al[mt][1], al[mt][2], al[mt][3],
                      aL + aoff + mt * 1280 + ks * 32);
#pragma unroll
            for (int j = 0; j < 2; j++)
                ldsm4(bh[j * 2][0], bh[j * 2][1], bh[j * 2 + 1][0], bh[j * 2 + 1][1],
                      bH + boff + j * 1280 + ks * 32);
#pragma unroll
            for (int j = 0; j < 2; j++)
                ldsm4(bl[j * 2][0], bl[j * 2][1], bl[j * 2 + 1][0], bl[j * 2 + 1][1],
                      bL + boff + j * 1280 + ks * 32);
#pragma unroll
            for (int mt = 0; mt < 4; mt++)
#pragma unroll
                for (int nt = 0; nt < 4; nt++) {
                    mma16816(acc[mt][nt], ah[mt], bh[nt]);
                    mma16816(acc[mt][nt], ah[mt], bl[nt]);
                    mma16816(acc[mt][nt], al[mt], bh[nt]);
                }
        }
        __syncthreads();
    }

    // ---- epilogue ----
    const int g = ln >> 2, t = ln & 3;
    const bool mirror = SYM && (m0 != n0);
#pragma unroll
    for (int mt = 0; mt < 4; mt++) {
#pragma unroll
        for (int nt = 0; nt < 4; nt++) {
            int m = m0 + wm + mt * 16 + g;
            int n = n0 + wn + nt * 8 + t * 2;
#pragma unroll
            for (int half = 0; half < 2; half++) {
                int mm = m + half * 8;
                float v0 = acc[mt][nt][half * 2 + 0];
                float v1 = acc[mt][nt][half * 2 + 1];
                size_t o = (size_t)mm * ldc + n;
                C[o] = v0; C[o + 1] = v1;
                if (mirror) {
                    C[(size_t)n * ldc + mm]       = v0;
                    C[(size_t)(n + 1) * ldc + mm] = v1;
                }
            }
        }
    }
}

// ================= implicit-im2col conv GEMM (MSFA) =======================
// A[m][k] implicit from NHWC xh/xl, K ordered k = tap*64 + c; B = g_Wh/g_Wl.
// EPI 0 (fused wc1+dil1, BN=128): n<64 -> g_h = relu(v+b0[n]);
//                                  n>=64 -> g_acc = relu(v+b1[n-64]) (unscaled)
// EPI 1 (dil branch, BN=64): g_acc[m][n] += wmap[m*4+wsel]*relu(v+b0[n])
template<int BN, int EPI>
__global__ void __launch_bounds__(32 * 2 * (BN / 32))
k_conv(const __nv_bfloat16* __restrict__ Xh, const __nv_bfloat16* __restrict__ Xl,
       const __nv_bfloat16* __restrict__ Wh, const __nv_bfloat16* __restrict__ Wl,
       float* __restrict__ O1, float* __restrict__ O2,
       const float* __restrict__ bias0, const float* __restrict__ bias1,
       const float* __restrict__ wmap, int wsel, int d)
{
    constexpr int BM = 128;
    constexpr int NWN = BN / 32;
    constexpr int T   = 32 * 2 * NWN;
    constexpr int AT  = BM * 80;
    constexpr int BT  = BN * 80;
    constexpr int STAGE = 2 * AT + 2 * BT;
    constexpr int CA = BM * 4, CB = BN * 4;
    constexpr int TC = 2 * (CA + CB);

    extern __shared__ char sm[];
    uint32_t sb = smem_to_u32(sm);

    const int m0 = blockIdx.x * BM;        // one image row: (b, y, x=0..127)
    const int b  = m0 >> 14;
    const int y  = (m0 >> 7) & 127;

    const int tid  = threadIdx.x;
    const int warp = tid >> 5, ln = tid & 31;
    const int wm = (warp / NWN) * 64;
    const int wn = (warp % NWN) * 32;

    float acc[4][4][4];
#pragma unroll
    for (int i = 0; i < 4; i++)
#pragma unroll
        for (int j = 0; j < 4; j++)
#pragma unroll
            for (int r = 0; r < 4; r++) acc[i][j][r] = 0.f;

    auto load_stage = [&](int s, int kt) {
        uint32_t base = sb + s * STAGE;
        int tap = kt / 64, c0 = kt & 63;
        int dy = (tap / 3 - 1) * d, dx = (tap % 3 - 1) * d;
        int sy = y + dy;
        bool rowok = (unsigned)sy < 128u;
        size_t rowpix = ((size_t)b * 128 + (rowok ? sy : 0)) * 128;
#pragma unroll
        for (int i = 0; i < TC / T; i++) {
            int idx = tid + i * T;
            if (idx < 2 * CA) {
                int hsel = (idx >= CA);
                int u = idx - hsel * CA;
                int r = u >> 2, kg = u & 3;
                int sxx = r + dx;
                bool ok = rowok && (unsigned)sxx < 128u;
                const __nv_bfloat16* base_g = hsel ? Xl : Xh;
                const __nv_bfloat16* src = base_g + (rowpix + (ok ? sxx : 0)) * 64
                                           + c0 + kg * 8;
                uint32_t dsm = base + hsel * AT + r * 80 + kg * 16;
                cp16z(dsm, src, ok ? 16 : 0);
            } else {
                int u = idx - 2 * CA;
                int hsel = (u >= CB);
                u -= hsel * CB;
                int r = u >> 2, kg = u & 3;
                const __nv_bfloat16* base_g = hsel ? Wl : Wh;
                const __nv_bfloat16* src = base_g + r * KC + kt + kg * 8;
                uint32_t dsm = base + 2 * AT + hsel * BT + r * 80 + kg * 16;
                cp16(dsm, src);
            }
        }
    };

    const uint32_t aoff = (uint32_t)((wm + ((ln >> 3) & 1) * 8 + (ln & 7)) * 80
                                     + ((ln >> 4) * 8) * 2);
    const uint32_t boff = (uint32_t)((wn + (ln >> 4) * 8 + (ln & 7)) * 80
                                     + (((ln >> 3) & 1) * 8) * 2);

    const int nc = KC >> 5;   // 18
    load_stage(0, 0);
    CP_COMMIT();

    for (int c = 0; c < nc; c++) {
        if (c + 1 < nc) {
            load_stage((c + 1) & 1, (c + 1) << 5);
            CP_COMMIT();
            CP_WAIT(1);
        } else {
            CP_WAIT(0);
        }
        __syncthreads();

        uint32_t stg = sb + (c & 1) * STAGE;
        uint32_t aH = stg, aL = stg + AT, bH = stg + 2 * AT, bL = stg + 2 * AT + BT;

#pragma unroll
        for (int ks = 0; ks < 2; ks++) {
            uint32_t ah[4][4], al[4][4], bh[4][2], bl[4][2];
#pragma unroll
            for (int mt = 0; mt < 4; mt++)
                ldsm4(ah[mt][0], ah[mt][1], ah[mt][2], ah[mt][3],
                      aH + aoff + mt * 1280 + ks * 32);
#pragma unroll
            for (int mt = 0; mt < 4; mt++)
                ldsm4(al[mt][0], al[mt][1], al[mt][2], al[mt][3],
                      aL + aoff + mt * 1280 + ks * 32);
#pragma unroll
            for (int j = 0; j < 2; j++)
                ldsm4(bh[j * 2][0], bh[j * 2][1], bh[j * 2 + 1][0], bh[j * 2 + 1][1],
                      bH + boff + j * 1280 + ks * 32);
#pragma unroll
            for (int j = 0; j < 2; j++)
                ldsm4(bl[j * 2][0], bl[j * 2][1], bl[j * 2 + 1][0], bl[j * 2 + 1][1],
                      bL + boff + j * 1280 + ks * 32);
#pragma unroll
            for (int mt = 0; mt < 4; mt++)
#pragma unroll
                for (int nt = 0; nt < 4; nt++) {
                    mma16816(acc[mt][nt], ah[mt], bh[nt]);
                    mma16816(acc[mt][nt], ah[mt], bl[nt]);
                    mma16816(acc[mt][nt], al[mt], bh[nt]);
                }
        }
        __syncthreads();
    }

    // ---- epilogue ----
    const int g = ln >> 2, t = ln & 3;
#pragma unroll
    for (int mt = 0; mt < 4; mt++) {
#pragma unroll
        for (int nt = 0; nt < 4; nt++) {
            int m = m0 + wm + mt * 16 + g;
            int n = wn + nt * 8 + t * 2;
#pragma unroll
            for (int half = 0; half < 2; half++) {
                int mm = m + half * 8;
                float v0 = acc[mt][nt][half * 2 + 0];
                float v1 = acc[mt][nt][half * 2 + 1];
                if (EPI == 0) {
                    if (n < 64) {
                        g_h[(size_t)mm * 64 + n]     = fmaxf(v0 + bias0[n], 0.f);
                        g_h[(size_t)mm * 64 + n + 1] = fmaxf(v1 + bias0[n + 1], 0.f);
                    } else {
                        g_acc[(size_t)mm * 64 + n - 64] = fmaxf(v0 + bias1[n - 64], 0.f);
                        g_acc[(size_t)mm * 64 + n - 63] = fmaxf(v1 + bias1[n - 63], 0.f);
                    }
                } else {
                    float w = wmap[(size_t)mm * 4 + wsel];
                    O1[(size_t)mm * 64 + n]     += w * fmaxf(v0 + bias0[n], 0.f);
                    O1[(size_t)mm * 64 + n + 1] += w * fmaxf(v1 + bias0[n + 1], 0.f);
                }
            }
        }
    }
}

// ---------------- norms from diag(S) --------------------------------------
__global__ void k_norms()
{
    int idx = blockIdx.x * 256 + threadIdx.x;
    if (idx >= B_ * NP) return;
    int b = idx >> 12, q = idx & (NP - 1);
    float d = g_S[((size_t)b * NP + q) * NP + q];
    float n = sqrtf(fmaxf(d, 0.f));
    g_inv[idx] = 1.0f / fmaxf(n, 1e-4f);
}

// ---------------- row softmax on S -> attnT (bf16 hi/lo) ------------------
__global__ void __launch_bounds__(256) k_softmax_rows()
{
    __shared__ float red[8];
    const int q = blockIdx.x & (NP - 1);
    const int b = blockIdx.x >> 12;
    const size_t base = ((size_t)b * NP + q) * NP;
    const float* invb = g_inv + b * NP;
    const int tid = threadIdx.x, lid = tid & 31, wid = tid >> 5;

    float v[16];
    float m = -3e38f;
#pragma unroll
    for (int i = 0; i < 16; i++) {
        int p = tid + i * 256;
        v[i] = invb[p] * g_S[base + p];
        m = fmaxf(m, v[i]);
    }
#pragma unroll
    for (int o = 16; o; o >>= 1) m = fmaxf(m, __shfl_xor_sync(~0u, m, o));
    if (lid == 0) red[wid] = m;
    __syncthreads();
    float mall = red[0];
#pragma unroll
    for (int i = 1; i < 8; i++) mall = fmaxf(mall, red[i]);
    __syncthreads();

    float s = 0.f;
#pragma unroll
    for (int i = 0; i < 16; i++) { v[i] = __expf(10.f * (v[i] - mall)); s += v[i]; }
#pragma unroll
    for (int o = 16; o; o >>= 1) s += __shfl_xor_sync(~0u, s, o);
    if (lid == 0) red[wid] = s;
    __syncthreads();
    float sall = 0.f;
#pragma unroll
    for (int i = 0; i < 8; i++) sall += red[i];
    float invS = 1.0f / sall;
#pragma unroll
    for (int i = 0; i < 16; i++) {
        int p = tid + i * 256;
        float val = fmaxf(v[i] * invS, 1e-8f);
        __nv_bfloat16 h, l;
        split2(val, h, l);
        g_ATh[base + p] = h;
        g_ATl[base + p] = l;
    }
}

// ---------------- col2im + /4 -> NHWC bf16 hi/lo (smem transpose) ---------
__global__ void __launch_bounds__(256) k_col2im_nhwc()
{
    __shared__ float tile[64 * 129];
    const int b  = blockIdx.x >> 7;
    const int oy = blockIdx.x & 127;
    const int tid = threadIdx.x;
    const float* Ub = g_U + (size_t)b * JB * NP;
    const int ky0 = (oy + 1) & 1;

#pragma unroll
    for (int i = 0; i < 32; i++) {
        int idx = tid + i * 256;
        int ox = idx & 127, c = idx >> 7;
        float r = 0.f;
        int kx0 = (ox + 1) & 1;
#pragma unroll
        for (int a = 0; a < 2; a++) {
            int ky = ky0 + 2 * a;
            int yy = (oy + 1 - ky) >> 1;
            if ((unsigned)yy < 64u) {
#pragma unroll
                for (int e = 0; e < 2; e++) {
                    int kx = kx0 + 2 * e;
                    int xx = (ox + 1 - kx) >> 1;
                    if ((unsigned)xx < 64u)
                        r += Ub[(size_t)(c * 16 + ky * 4 + kx) * NP + yy * 64 + xx];
                }
            }
        }
        tile[c * 129 + ox] = 0.25f * r;
    }
    __syncthreads();

    const size_t rowbase = ((size_t)b * 128 + oy) * 128;
#pragma unroll
    for (int i = 0; i < 32; i++) {
        int idx = tid + i * 256;
        int c = idx & 63, x = idx >> 6;
        size_t o = (rowbase + x) * 64 + c;
        __nv_bfloat16 h, l;
        split2(tile[c * 129 + x], h, l);
        g_xh[o] = h;
        g_xl[o] = l;
    }
}

// ---------------- conv weight repack+split: rows [rowofs..rowofs+64) ------
// dst[n][tap*64 + c] = w[n][c*9 + tap]
__global__ void k_wsplit_conv(const float* __restrict__ w, int rowofs)
{
    int idx = blockIdx.x * 256 + threadIdx.x;
    if (idx >= C_ * KC) return;
    int n = idx / KC, k = idx % KC;
    int tap = k >> 6, c = k & 63;
    float v = w[n * KC + c * 9 + tap];
    split2(v, g_Wh[(rowofs + n) * KC + k], g_Wl[(rowofs + n) * KC + k]);
}

// ---------------- wc2 1x1 conv + relu + softmax(4) ------------------------
__global__ void k_wc2_softmax(const float* __restrict__ w, const float* __restrict__ bias)
{
    __shared__ float sw[256];
    __shared__ float sb[4];
    int t = threadIdx.x;
    if (t < 256) sw[t] = w[t];
    if (t < 4)   sb[t] = bias[t];
    __syncthreads();
    int m = blockIdx.x * 256 + t;
    const float* hr = g_h + (size_t)m * 64;
    float a0 = sb[0], a1 = sb[1], a2 = sb[2], a3 = sb[3];
#pragma unroll 4
    for (int c = 0; c < 64; c++) {
        float hv = hr[c];
        a0 = fmaf(sw[c], hv, a0);
        a1 = fmaf(sw[64 + c], hv, a1);
        a2 = fmaf(sw[128 + c], hv, a2);
        a3 = fmaf(sw[192 + c], hv, a3);
    }
    a0 = fmaxf(a0, 0.f); a1 = fmaxf(a1, 0.f); a2 = fmaxf(a2, 0.f); a3 = fmaxf(a3, 0.f);
    float mx = fmaxf(fmaxf(a0, a1), fmaxf(a2, a3));
    float e0 = __expf(a0 - mx), e1 = __expf(a1 - mx), e2 = __expf(a2 - mx), e3 = __expf(a3 - mx);
    float r = 1.0f / (e0 + e1 + e2 + e3);
    g_wmap[(size_t)m * 4 + 0] = e0 * r;
    g_wmap[(size_t)m * 4 + 1] = e1 * r;
    g_wmap[(size_t)m * 4 + 2] = e2 * r;
    g_wmap[(size_t)m * 4 + 3] = e3 * r;
}

// ---------------- scale feat1 (already in g_acc) by wmap[:,0] -------------
__global__ void k_scale0()
{
    int idx = blockIdx.x * 256 + threadIdx.x;
    g_acc[idx] *= g_wmap[(size_t)(idx >> 6) * 4];
}

// ---------------- final transpose (m,c) -> NCHW ---------------------------
__global__ void k_transpose_out(float* __restrict__ out)
{
    __shared__ float tile[32][33];
    int b = blockIdx.z;
    int c0 = blockIdx.y * 32;
    int m0 = blockIdx.x * 32;
    int tx = threadIdx.x, ty = threadIdx.y;
#pragma unroll
    for (int i = 0; i < 4; i++) {
        int mm = m0 + ty + i * 8;
        tile[ty + i * 8][tx] = g_acc[((size_t)b * 16384 + mm) * 64 + c0 + tx];
    }
    __syncthreads();
#pragma unroll
    for (int i = 0; i < 4; i++) {
        int cc = c0 + ty + i * 8;
        out[((size_t)b * 64 + cc) * 16384 + m0 + tx] = tile[tx][ty + i * 8];
    }
}

// ---------------- launch ---------------------------------------------------
extern "C" void kernel_launch(void* const* d_in, const int* /*in_sizes*/, int /*n_in*/,
                              void* d_out, int /*out_size*/)
{
    const float* bg    = (const float*)d_in[0];
    const float* fg    = (const float*)d_in[1];
    const float* dil_w = (const float*)d_in[2];
    const float* dil_b = (const float*)d_in[3];
    const float* wc1_w = (const float*)d_in[4];
    const float* wc1_b = (const float*)d_in[5];
    const float* wc2_w = (const float*)d_in[6];
    const float* wc2_b = (const float*)d_in[7];
    float* out = (float*)d_out;

    __nv_bfloat16 *pPth, *pPtl, *pATh, *pATl, *pBgth, *pBgtl, *pXh, *pXl, *pWh, *pWl;
    float *pS, *pU, *pH, *pAcc, *pWmap;
    cudaGetSymbolAddress((void**)&pPth,  g_Pth);
    cudaGetSymbolAddress((void**)&pPtl,  g_Ptl);
    cudaGetSymbolAddress((void**)&pS,    g_S);
    cudaGetSymbolAddress((void**)&pATh,  g_ATh);
    cudaGetSymbolAddress((void**)&pATl,  g_ATl);
    cudaGetSymbolAddress((void**)&pBgth, g_Bgth);
    cudaGetSymbolAddress((void**)&pBgtl, g_Bgtl);
    cudaGetSymbolAddress((void**)&pU,    g_U);
    cudaGetSymbolAddress((void**)&pXh,   g_xh);
    cudaGetSymbolAddress((void**)&pXl,   g_xl);
    cudaGetSymbolAddress((void**)&pWh,   g_Wh);
    cudaGetSymbolAddress((void**)&pWl,   g_Wl);
    cudaGetSymbolAddress((void**)&pH,    g_h);
    cudaGetSymbolAddress((void**)&pAcc,  g_acc);
    cudaGetSymbolAddress((void**)&pWmap, g_wmap);

    const int SM128 = 2 * (2 * 128 * 80 + 2 * 128 * 80);   // 81920
    const int SM64  = 2 * (2 * 128 * 80 + 2 * 64 * 80);    // 61440
    cudaFuncSetAttribute(k_hgemm<128, 128, 1>, cudaFuncAttributeMaxDynamicSharedMemorySize, SM128);
    cudaFuncSetAttribute(k_hgemm<128, 128, 0>, cudaFuncAttributeMaxDynamicSharedMemorySize, SM128);
    cudaFuncSetAttribute(k_conv<128, 0>, cudaFuncAttributeMaxDynamicSharedMemorySize, SM128);
    cudaFuncSetAttribute(k_conv<64, 1>,  cudaFuncAttributeMaxDynamicSharedMemorySize, SM64);

    // ---- RAL ----
    k_resize<<<(B_ * C_ * HS * HS + 255) / 256, 256>>>(fg);
    k_build_Pt<<<(int)(((size_t)B_ * NP * KP + 255) / 256), 256>>>();

    // S = Pt * Pt^T (Gram, symmetric: 528 upper-tri blocks + mirror)
    k_hgemm<128, 128, 1><<<dim3(528, 1, B_), 256, SM128>>>(
        pPth, pPtl, pPth, pPtl, pS, KP, KP, KP, NP,
        (size_t)NP * KP, (size_t)NP * KP, (size_t)NP * NP);

    k_norms<<<(B_ * NP + 255) / 256, 256>>>();
    k_softmax_rows<<<B_ * NP, 256>>>();

    k_build_Bgt<<<(int)(((size_t)B_ * JB * NP + 255) / 256), 256>>>(bg);

    // U[j][q] = sum_p Bgt[j][p] * attnT[q][p]; K = 4096
    k_hgemm<128, 128, 0><<<dim3(NP / 128, JB / 128, B_), 256, SM128>>>(
        pBgth, pBgtl, pATh, pATl, pU, NP, NP, NP, NP,
        (size_t)JB * NP, (size_t)NP * NP, (size_t)JB * NP);

    k_col2im_nhwc<<<B_ * H_, 256>>>();

    // ---- MSFA ----
    // fused wc1 + dilation-1 branch (shared implicit-im2col A, d=1)
    k_wsplit_conv<<<(C_ * KC + 255) / 256, 256>>>(wc1_w, 0);
    k_wsplit_conv<<<(C_ * KC + 255) / 256, 256>>>(dil_w, 64);
    k_conv<128, 0><<<MC / 128, 256, SM128>>>(
        pXh, pXl, pWh, pWl, pH, pAcc, wc1_b, dil_b, nullptr, 0, 1);

    k_wc2_softmax<<<MC / 256, 256>>>(wc2_w, wc2_b);
    k_scale0<<<(MC * 64) / 256, 256>>>();

    for (int i = 1; i < 4; i++) {
        k_wsplit_conv<<<(C_ * KC + 255) / 256, 256>>>(dil_w + (size_t)i * KC * C_, 0);
        k_conv<64, 1><<<MC / 128, 128, SM64>>>(
            pXh, pXl, pWh, pWl, pAcc, nullptr, dil_b + i * C_, nullptr,
            pWmap, i, 1 << i);
    }

    k_transpose_out<<<dim3(16384 / 32, 2, B_), dim3(32, 8)>>>(out);
}

// round 5
// speedup vs baseline: 6.1538x; 2.1132x over previous
#include <cuda_runtime.h>
#include <cuda_bf16.h>
#include <cstddef>
#include <cstdint>

// ---------------- problem dims ----------------
#define B_  4
#define C_  64
#define H_  128
#define W_  128
#define HS  64            // fg half-size
#define NP  4096          // 64*64 patches / positions
#define KP  576           // 64ch * 3*3
#define MC  65536         // msfa positions: 4*128*128
#define KC  576           // msfa conv K

// ================= base-ISA helpers =======================================
__device__ __forceinline__ uint32_t smem_to_u32(const void* smem_ptr) {
    uint32_t addr;
    asm("{ .reg .u64 tmp; cvta.to.shared.u64 tmp, %1; cvt.u32.u64 %0, tmp; }"
        : "=r"(addr) : "l"(smem_ptr));
    return addr;
}
__device__ __forceinline__ void cp16(uint32_t dst, const void* src) {
    asm volatile("cp.async.cg.shared.global [%0], [%1], 16;"
                 :: "r"(dst), "l"(src));
}
__device__ __forceinline__ void cp16z(uint32_t dst, const void* src, int sz) {
    asm volatile("cp.async.cg.shared.global [%0], [%1], 16, %2;"
                 :: "r"(dst), "l"(src), "r"(sz));
}
#define CP_COMMIT() asm volatile("cp.async.commit_group;" ::: "memory")
#define CP_WAIT(n)  asm volatile("cp.async.wait_group %0;" :: "n"(n) : "memory")

__device__ __forceinline__ void ldsm4(uint32_t& a, uint32_t& b, uint32_t& c, uint32_t& d,
                                      uint32_t addr) {
    asm volatile("ldmatrix.sync.aligned.m8n8.x4.shared.b16 {%0,%1,%2,%3}, [%4];"
                 : "=r"(a), "=r"(b), "=r"(c), "=r"(d) : "r"(addr));
}
__device__ __forceinline__ void mma16816(float* c, const uint32_t* a, const uint32_t* b) {
    asm volatile(
        "mma.sync.aligned.m16n8k16.row.col.f32.bf16.bf16.f32 "
        "{%0,%1,%2,%3}, {%4,%5,%6,%7}, {%8,%9}, {%0,%1,%2,%3};"
        : "+f"(c[0]), "+f"(c[1]), "+f"(c[2]), "+f"(c[3])
        : "r"(a[0]), "r"(a[1]), "r"(a[2]), "r"(a[3]), "r"(b[0]), "r"(b[1]));
}

// ---------------- scratch (static device globals; no allocation) ----------
static __device__ __align__(16) float g_fgs[(size_t)B_ * C_ * HS * HS];
static __device__ __align__(16) __nv_bfloat16 g_Pth[(size_t)B_ * NP * KP];
static __device__ __align__(16) __nv_bfloat16 g_Ptl[(size_t)B_ * NP * KP];
static __device__ __align__(16) float g_S[(size_t)B_ * NP * NP];       // Gram [q][p]
static __device__ __align__(16) float g_inv[B_ * NP];
static __device__ __align__(16) float g_Bg[(size_t)B_ * NP * 1024];    // [b][p][tap*64+c]
static __device__ __align__(16) float g_colsum[B_ * 1024];
static __device__ __align__(16) float g_cspart[B_ * 16 * 1024];
static __device__ int               g_scnt[B_ * NP];
static __device__ __align__(16) int   g_sidx[(size_t)B_ * NP * NP / 1]; // cap 4096/row
static __device__ __align__(16) float g_sval[(size_t)B_ * NP * NP / 1];
static __device__ __align__(16) float g_U[(size_t)B_ * NP * 1024];     // [b][q][tap*64+c]
static __device__ __align__(16) __nv_bfloat16 g_xh[(size_t)B_ * H_ * W_ * C_]; // NHWC hi
static __device__ __align__(16) __nv_bfloat16 g_xl[(size_t)B_ * H_ * W_ * C_]; // NHWC lo
static __device__ __align__(16) __nv_bfloat16 g_Wh[128 * KC];
static __device__ __align__(16) __nv_bfloat16 g_Wl[128 * KC];
static __device__ __align__(16) float g_h[(size_t)MC * C_];
static __device__ __align__(16) float g_wmap[(size_t)MC * 4];
static __device__ __align__(16) float g_acc[(size_t)MC * C_];

__device__ __forceinline__ void split2(float v, __nv_bfloat16& h, __nv_bfloat16& l)
{
    h = __float2bfloat16(v);
    l = __float2bfloat16(v - __bfloat162float(h));
}

// ---------------- bilinear half-resize (align_corners) --------------------
__global__ void k_resize(const float* __restrict__ fg)
{
    int idx = blockIdx.x * 256 + threadIdx.x;
    if (idx >= B_ * C_ * HS * HS) return;
    int x = idx & 63, y = (idx >> 6) & 63;
    int bc = idx >> 12;
    const float* src = fg + (size_t)bc * H_ * W_;
    float cy = (float)y * (127.0f / 63.0f);
    float cx = (float)x * (127.0f / 63.0f);
    int iy = (int)cy; if (iy > 127) iy = 127;
    int ix = (int)cx; if (ix > 127) ix = 127;
    int iy1 = min(iy + 1, 127), ix1 = min(ix + 1, 127);
    float wy = cy - (float)iy, wx = cx - (float)ix;
    float v00 = src[iy * 128 + ix],  v01 = src[iy * 128 + ix1];
    float v10 = src[iy1 * 128 + ix], v11 = src[iy1 * 128 + ix1];
    g_fgs[idx] = (1.f - wy) * ((1.f - wx) * v00 + wx * v01)
               +        wy  * ((1.f - wx) * v10 + wx * v11);
}

// ---------------- fg im2col (q-major, split bf16): Pt[b][q][k] ------------
__global__ void k_build_Pt()
{
    size_t idx = (size_t)blockIdx.x * 256 + threadIdx.x;
    if (idx >= (size_t)B_ * NP * KP) return;
    int k = (int)(idx % KP);
    size_t t = idx / KP;
    int q = (int)(t & (NP - 1));
    int b = (int)(t >> 12);
    int x = q & 63, y = q >> 6;
    int dx = k % 3, dy = (k / 3) % 3, c = k / 9;
    int sy = y + dy - 1, sx = x + dx - 1;
    float v = 0.f;
    if ((unsigned)sy < 64u && (unsigned)sx < 64u)
        v = g_fgs[((size_t)(b * C_ + c) << 12) + sy * 64 + sx];
    split2(v, g_Pth[idx], g_Ptl[idx]);
}

// ---------------- bg patches fp32: Bg[b][p][tap*64+c] ----------------------
__global__ void k_build_Bg(const float* __restrict__ bg)
{
    size_t idx = (size_t)blockIdx.x * 256 + threadIdx.x;
    if (idx >= (size_t)B_ * NP * 1024) return;
    int j = (int)(idx & 1023);
    int p = (int)((idx >> 10) & 4095);
    int b = (int)(idx >> 22);
    int tap = j >> 6, c = j & 63, ky = tap >> 2, kx = tap & 3;
    int py = p >> 6, px = p & 63;
    int sy = 2 * py + ky - 1, sx = 2 * px + kx - 1;
    float v = 0.f;
    if ((unsigned)sy < 128u && (unsigned)sx < 128u)
        v = bg[(((size_t)b * 64 + c) * 128 + sy) * 128 + sx];
    g_Bg[idx] = v;
}

// ---------------- column sums of Bg (two-stage, deterministic) -------------
__global__ void k_colsum_part()   // grid (4 jchunk, 16 slice, 4 b), 256 thr
{
    int j  = blockIdx.x * 256 + threadIdx.x;
    int sl = blockIdx.y, b = blockIdx.z;
    const float* Bgb = g_Bg + ((size_t)b * NP + sl * 256) * 1024 + j;
    float s = 0.f;
#pragma unroll 8
    for (int p = 0; p < 256; p++) s += Bgb[(size_t)p * 1024];
    g_cspart[((b * 16 + sl) << 10) + j] = s;
}
__global__ void k_colsum_red()    // grid 16, 256 thr
{
    int idx = blockIdx.x * 256 + threadIdx.x;   // b*1024 + j
    int b = idx >> 10, j = idx & 1023;
    float s = 0.f;
#pragma unroll
    for (int sl = 0; sl < 16; sl++) s += g_cspart[((b * 16 + sl) << 10) + j];
    g_colsum[idx] = s;
}

// ================= split-bf16 warp-MMA GEMM (Gram, symmetric) =============
template<int BM, int BN>
__global__ void __launch_bounds__(256)
k_hgemm_sym(const __nv_bfloat16* __restrict__ Ah, const __nv_bfloat16* __restrict__ Al,
            float* __restrict__ C, int K, int lda, int ldc,
            size_t sA, size_t sC)
{
    constexpr int NWN = BN / 32;
    constexpr int T   = 32 * (BM / 64) * NWN;
    constexpr int AT  = BM * 80;
    constexpr int BT  = BN * 80;
    constexpr int STAGE = 2 * AT + 2 * BT;
    constexpr int CA = BM * 4, CB = BN * 4;
    constexpr int TC = 2 * (CA + CB);

    extern __shared__ char sm[];
    uint32_t sb = smem_to_u32(sm);

    Ah += blockIdx.z * sA; Al += blockIdx.z * sA;
    C  += blockIdx.z * sC;

    int tt = blockIdx.x, bi = 0, rl = ldc / BM;
    while (tt >= rl) { tt -= rl; rl--; bi++; }
    const int m0 = bi * BM;
    const int n0 = (bi + tt) * BN;

    const int tid  = threadIdx.x;
    const int warp = tid >> 5, ln = tid & 31;
    const int wm = (warp / NWN) * 64;
    const int wn = (warp % NWN) * 32;

    float acc[4][4][4];
#pragma unroll
    for (int i = 0; i < 4; i++)
#pragma unroll
        for (int j = 0; j < 4; j++)
#pragma unroll
            for (int r = 0; r < 4; r++) acc[i][j][r] = 0.f;

    auto load_stage = [&](int s, int kt) {
        uint32_t base = sb + s * STAGE;
#pragma unroll
        for (int i = 0; i < TC / T; i++) {
            int idx = tid + i * T;
            int r, kg;
            uint32_t dsm;
            const __nv_bfloat16* g;
            if (idx < CA) {
                r = idx >> 2; kg = idx & 3;
                dsm = base + r * 80 + kg * 16;
                g = Ah + (size_t)(m0 + r) * lda + kt + kg * 8;
            } else if (idx < 2 * CA) {
                int u = idx - CA; r = u >> 2; kg = u & 3;
                dsm = base + AT + r * 80 + kg * 16;
                g = Al + (size_t)(m0 + r) * lda + kt + kg * 8;
            } else if (idx < 2 * CA + CB) {
                int u = idx - 2 * CA; r = u >> 2; kg = u & 3;
                dsm = base + 2 * AT + r * 80 + kg * 16;
                g = Ah + (size_t)(n0 + r) * lda + kt + kg * 8;
            } else {
                int u = idx - 2 * CA - CB; r = u >> 2; kg = u & 3;
                dsm = base + 2 * AT + BT + r * 80 + kg * 16;
                g = Al + (size_t)(n0 + r) * lda + kt + kg * 8;
            }
            cp16(dsm, g);
        }
    };

    const uint32_t aoff = (uint32_t)((wm + ((ln >> 3) & 1) * 8 + (ln & 7)) * 80
                                     + ((ln >> 4) * 8) * 2);
    const uint32_t boff = (uint32_t)((wn + (ln >> 4) * 8 + (ln & 7)) * 80
                                     + (((ln >> 3) & 1) * 8) * 2);

    const int nc = K >> 5;
    load_stage(0, 0);
    CP_COMMIT();

    for (int c = 0; c < nc; c++) {
        if (c + 1 < nc) {
            load_stage((c + 1) & 1, (c + 1) << 5);
            CP_COMMIT();
            CP_WAIT(1);
        } else {
            CP_WAIT(0);
        }
        __syncthreads();

        uint32_t stg = sb + (c & 1) * STAGE;
        uint32_t aH = stg, aL = stg + AT, bH = stg + 2 * AT, bL = stg + 2 * AT + BT;

#pragma unroll
        for (int ks = 0; ks < 2; ks++) {
            uint32_t ah[4][4], al[4][4], bh[4][2], bl[4][2];
#pragma unroll
            for (int mt = 0; mt < 4; mt++)
                ldsm4(ah[mt][0], ah[mt][1], ah[mt][2], ah[mt][3],
                      aH + aoff + mt * 1280 + ks * 32);
#pragma unroll
            for (int mt = 0; mt < 4; mt++)
                ldsm4(al[mt][0], al[mt][1], al[mt][2], al[mt][3],
                      aL + aoff + mt * 1280 + ks * 32);
#pragma unroll
            for (int j = 0; j < 2; j++)
                ldsm4(bh[j * 2][0], bh[j * 2][1], bh[j * 2 + 1][0], bh[j * 2 + 1][1],
                      bH + boff + j * 1280 + ks * 32);
#pragma unroll
            for (int j = 0; j < 2; j++)
                ldsm4(bl[j * 2][0], bl[j * 2][1], bl[j * 2 + 1][0], bl[j * 2 + 1][1],
                      bL + boff + j * 1280 + ks * 32);
#pragma unroll
            for (int mt = 0; mt < 4; mt++)
#pragma unroll
                for (int nt = 0; nt < 4; nt++) {
                    mma16816(acc[mt][nt], ah[mt], bh[nt]);
                    mma16816(acc[mt][nt], ah[mt], bl[nt]);
                    mma16816(acc[mt][nt], al[mt], bh[nt]);
                }
        }
        __syncthreads();
    }

    const int g = ln >> 2, t = ln & 3;
    const bool mirror = (m0 != n0);
#pragma unroll
    for (int mt = 0; mt < 4; mt++) {
#pragma unroll
        for (int nt = 0; nt < 4; nt++) {
            int m = m0 + wm + mt * 16 + g;
            int n = n0 + wn + nt * 8 + t * 2;
#pragma unroll
            for (int half = 0; half < 2; half++) {
                int mm = m + half * 8;
                float v0 = acc[mt][nt][half * 2 + 0];
                float v1 = acc[mt][nt][half * 2 + 1];
                size_t o = (size_t)mm * ldc + n;
                C[o] = v0; C[o + 1] = v1;
                if (mirror) {
                    C[(size_t)n * ldc + mm]       = v0;
                    C[(size_t)(n + 1) * ldc + mm] = v1;
                }
            }
        }
    }
}

// ================= implicit-im2col conv GEMM (MSFA) =======================
template<int BN, int EPI>
__global__ void __launch_bounds__(32 * 2 * (BN / 32))
k_conv(const __nv_bfloat16* __restrict__ Xh, const __nv_bfloat16* __restrict__ Xl,
       const __nv_bfloat16* __restrict__ Wh, const __nv_bfloat16* __restrict__ Wl,
       float* __restrict__ O1,
       const float* __restrict__ bias0, const float* __restrict__ bias1,
       const float* __restrict__ wmap, int wsel, int d)
{
    constexpr int BM = 128;
    constexpr int NWN = BN / 32;
    constexpr int T   = 32 * 2 * NWN;
    constexpr int AT  = BM * 80;
    constexpr int BT  = BN * 80;
    constexpr int STAGE = 2 * AT + 2 * BT;
    constexpr int CA = BM * 4, CB = BN * 4;
    constexpr int TC = 2 * (CA + CB);

    extern __shared__ char sm[];
    uint32_t sb = smem_to_u32(sm);

    const int m0 = blockIdx.x * BM;
    const int b  = m0 >> 14;
    const int y  = (m0 >> 7) & 127;

    const int tid  = threadIdx.x;
    const int warp = tid >> 5, ln = tid & 31;
    const int wm = (warp / NWN) * 64;
    const int wn = (warp % NWN) * 32;

    float acc[4][4][4];
#pragma unroll
    for (int i = 0; i < 4; i++)
#pragma unroll
        for (int j = 0; j < 4; j++)
#pragma unroll
            for (int r = 0; r < 4; r++) acc[i][j][r] = 0.f;

    auto load_stage = [&](int s, int kt) {
        uint32_t base = sb + s * STAGE;
        int tap = kt / 64, c0 = kt & 63;
        int dy = (tap / 3 - 1) * d, dx = (tap % 3 - 1) * d;
        int sy = y + dy;
        bool rowok = (unsigned)sy < 128u;
        size_t rowpix = ((size_t)b * 128 + (rowok ? sy : 0)) * 128;
#pragma unroll
        for (int i = 0; i < TC / T; i++) {
            int idx = tid + i * T;
            if (idx < 2 * CA) {
                int hsel = (idx >= CA);
                int u = idx - hsel * CA;
                int r = u >> 2, kg = u & 3;
                int sxx = r + dx;
                bool ok = rowok && (unsigned)sxx < 128u;
                const __nv_bfloat16* base_g = hsel ? Xl : Xh;
                const __nv_bfloat16* src = base_g + (rowpix + (ok ? sxx : 0)) * 64
                                           + c0 + kg * 8;
                uint32_t dsm = base + hsel * AT + r * 80 + kg * 16;
                cp16z(dsm, src, ok ? 16 : 0);
            } else {
                int u = idx - 2 * CA;
                int hsel = (u >= CB);
                u -= hsel * CB;
                int r = u >> 2, kg = u & 3;
                const __nv_bfloat16* base_g = hsel ? Wl : Wh;
                const __nv_bfloat16* src = base_g + r * KC + kt + kg * 8;
                uint32_t dsm = base + 2 * AT + hsel * BT + r * 80 + kg * 16;
                cp16(dsm, src);
            }
        }
    };

    const uint32_t aoff = (uint32_t)((wm + ((ln >> 3) & 1) * 8 + (ln & 7)) * 80
                                     + ((ln >> 4) * 8) * 2);
    const uint32_t boff = (uint32_t)((wn + (ln >> 4) * 8 + (ln & 7)) * 80
                                     + (((ln >> 3) & 1) * 8) * 2);

    const int nc = KC >> 5;   // 18
    load_stage(0, 0);
    CP_COMMIT();

    for (int c = 0; c < nc; c++) {
        if (c + 1 < nc) {
            load_stage((c + 1) & 1, (c + 1) << 5);
            CP_COMMIT();
            CP_WAIT(1);
        } else {
            CP_WAIT(0);
        }
        __syncthreads();

        uint32_t stg = sb + (c & 1) * STAGE;
        uint32_t aH = stg, aL = stg + AT, bH = stg + 2 * AT, bL = stg + 2 * AT + BT;

#pragma unroll
        for (int ks = 0; ks < 2; ks++) {
            uint32_t ah[4][4], al[4][4], bh[4][2], bl[4][2];
#pragma unroll
            for (int mt = 0; mt < 4; mt++)
                ldsm4(ah[mt][0], ah[mt][1], ah[mt][2], ah[mt][3],
                      aH + aoff + mt * 1280 + ks * 32);
#pragma unroll
            for (int mt = 0; mt < 4; mt++)
                ldsm4(al[mt][0], al[mt][1], al[mt][2], al[mt][3],
                      aL + aoff + mt * 1280 + ks * 32);
#pragma unroll
            for (int j = 0; j < 2; j++)
                ldsm4(bh[j * 2][0], bh[j * 2][1], bh[j * 2 + 1][0], bh[j * 2 + 1][1],
                      bH + boff + j * 1280 + ks * 32);
#pragma unroll
            for (int j = 0; j < 2; j++)
                ldsm4(bl[j * 2][0], bl[j * 2][1], bl[j * 2 + 1][0], bl[j * 2 + 1][1],
                      bL + boff + j * 1280 + ks * 32);
#pragma unroll
            for (int mt = 0; mt < 4; mt++)
#pragma unroll
                for (int nt = 0; nt < 4; nt++) {
                    mma16816(acc[mt][nt], ah[mt], bh[nt]);
                    mma16816(acc[mt][nt], ah[mt], bl[nt]);
                    mma16816(acc[mt][nt], al[mt], bh[nt]);
                }
        }
        __syncthreads();
    }

    const int g = ln >> 2, t = ln & 3;
#pragma unroll
    for (int mt = 0; mt < 4; mt++) {
#pragma unroll
        for (int nt = 0; nt < 4; nt++) {
            int m = m0 + wm + mt * 16 + g;
            int n = wn + nt * 8 + t * 2;
#pragma unroll
            for (int half = 0; half < 2; half++) {
                int mm = m + half * 8;
                float v0 = acc[mt][nt][half * 2 + 0];
                float v1 = acc[mt][nt][half * 2 + 1];
                if (EPI == 0) {
                    if (n < 64) {
                        g_h[(size_t)mm * 64 + n]     = fmaxf(v0 + bias0[n], 0.f);
                        g_h[(size_t)mm * 64 + n + 1] = fmaxf(v1 + bias0[n + 1], 0.f);
                    } else {
                        g_acc[(size_t)mm * 64 + n - 64] = fmaxf(v0 + bias1[n - 64], 0.f);
                        g_acc[(size_t)mm * 64 + n - 63] = fmaxf(v1 + bias1[n - 63], 0.f);
                    }
                } else {
                    float w = wmap[(size_t)mm * 4 + wsel];
                    O1[(size_t)mm * 64 + n]     += w * fmaxf(v0 + bias0[n], 0.f);
                    O1[(size_t)mm * 64 + n + 1] += w * fmaxf(v1 + bias0[n + 1], 0.f);
                }
            }
        }
    }
}

// ---------------- norms from diag(S) --------------------------------------
__global__ void k_norms()
{
    int idx = blockIdx.x * 256 + threadIdx.x;
    if (idx >= B_ * NP) return;
    int b = idx >> 12, q = idx & (NP - 1);
    float d = g_S[((size_t)b * NP + q) * NP + q];
    float n = sqrtf(fmaxf(d, 0.f));
    g_inv[idx] = 1.0f / fmaxf(n, 1e-4f);
}

// ---------------- row softmax on S -> deterministic sparse lists ----------
__global__ void __launch_bounds__(256) k_softmax_sparse()
{
    __shared__ float red[8];
    __shared__ int warp_cnt[8];
    __shared__ int base_cnt;
    const int bq = blockIdx.x;
    const int q = bq & (NP - 1);
    const int b = bq >> 12;
    const size_t base = ((size_t)b * NP + q) * NP;
    const float* invb = g_inv + b * NP;
    const int tid = threadIdx.x, lid = tid & 31, wid = tid >> 5;

    float v[16];
    float m = -3e38f;
#pragma unroll
    for (int i = 0; i < 16; i++) {
        int p = i * 256 + tid;
        v[i] = invb[p] * g_S[base + p];
        m = fmaxf(m, v[i]);
    }
#pragma unroll
    for (int o = 16; o; o >>= 1) m = fmaxf(m, __shfl_xor_sync(~0u, m, o));
    if (lid == 0) red[wid] = m;
    __syncthreads();
    float mall = red[0];
#pragma unroll
    for (int i = 1; i < 8; i++) mall = fmaxf(mall, red[i]);
    __syncthreads();

    float s = 0.f;
#pragma unroll
    for (int i = 0; i < 16; i++) { v[i] = __expf(10.f * (v[i] - mall)); s += v[i]; }
#pragma unroll
    for (int o = 16; o; o >>= 1) s += __shfl_xor_sync(~0u, s, o);
    if (lid == 0) red[wid] = s;
    __syncthreads();
    float sall = 0.f;
#pragma unroll
    for (int i = 0; i < 8; i++) sall += red[i];
    float invS = 1.0f / sall;

    if (tid == 0) base_cnt = 0;
    __syncthreads();

    const size_t lbase = (size_t)bq * 4096;
    for (int i = 0; i < 16; i++) {
        int p = i * 256 + tid;
        float w = v[i] * invS;
        bool hit = w > 1e-6f;
        unsigned bal = __ballot_sync(0xffffffffu, hit);
        if (lid == 0) warp_cnt[wid] = __popc(bal);
        __syncthreads();
        int woff = base_cnt;
        for (int j = 0; j < wid; j++) woff += warp_cnt[j];
        if (hit) {
            int rank = woff + __popc(bal & ((1u << lid) - 1u));
            g_sidx[lbase + rank] = p;
            g_sval[lbase + rank] = w - 1e-8f;
        }
        __syncthreads();
        if (tid == 0) {
            int t = 0;
            for (int j = 0; j < 8; j++) t += warp_cnt[j];
            base_cnt += t;
        }
        __syncthreads();
    }
    if (tid == 0) g_scnt[bq] = base_cnt;
}

// ---------------- sparse U: U[b][q][j] = sum w_p Bg[p][j] + 1e-8*colsum ---
__global__ void __launch_bounds__(256) k_sparseU()
{
    const int bq = blockIdx.x;
    const int b = bq >> 12;
    const int tid = threadIdx.x;
    const int cnt = g_scnt[bq];

    float acc[4];
#pragma unroll
    for (int r = 0; r < 4; r++)
        acc[r] = 1e-8f * g_colsum[b * 1024 + r * 256 + tid];

    const float* Bgb = g_Bg + (size_t)b * NP * 1024;
    const size_t lbase = (size_t)bq * 4096;
    for (int e = 0; e < cnt; e++) {
        int p = g_sidx[lbase + e];
        float w = g_sval[lbase + e];
        const float* row = Bgb + (size_t)p * 1024;
#pragma unroll
        for (int r = 0; r < 4; r++)
            acc[r] = fmaf(w, row[r * 256 + tid], acc[r]);
    }
#pragma unroll
    for (int r = 0; r < 4; r++)
        g_U[(size_t)bq * 1024 + r * 256 + tid] = acc[r];
}

// ---------------- col2im + /4 -> NHWC bf16 hi/lo (direct) -----------------
__global__ void k_col2im_nhwc()
{
    int idx = blockIdx.x * 256 + threadIdx.x;   // (b, oy, ox, c) c fastest
    int c = idx & 63, ox = (idx >> 6) & 127, oy = (idx >> 13) & 127, b = idx >> 20;
    float r = 0.f;
    int ky0 = (oy + 1) & 1, kx0 = (ox + 1) & 1;
#pragma unroll
    for (int a = 0; a < 2; a++) {
        int ky = ky0 + 2 * a;
        int y = (oy + 1 - ky) >> 1;
        if ((unsigned)y < 64u) {
#pragma unroll
            for (int e = 0; e < 2; e++) {
                int kx = kx0 + 2 * e;
                int xx = (ox + 1 - kx) >> 1;
                if ((unsigned)xx < 64u)
                    r += g_U[(size_t)((b << 12) + (y << 6) + xx) * 1024
                             + (ky * 4 + kx) * 64 + c];
            }
        }
    }
    __nv_bfloat16 h, l;
    split2(0.25f * r, h, l);
    g_xh[idx] = h;
    g_xl[idx] = l;
}

// ---------------- conv weight repack+split: rows [rowofs..rowofs+64) ------
__global__ void k_wsplit_conv(const float* __restrict__ w, int rowofs)
{
    int idx = blockIdx.x * 256 + threadIdx.x;
    if (idx >= C_ * KC) return;
    int n = idx / KC, k = idx % KC;
    int tap = k >> 6, c = k & 63;
    float v = w[n * KC + c * 9 + tap];
    split2(v, g_Wh[(rowofs + n) * KC + k], g_Wl[(rowofs + n) * KC + k]);
}

// ---------------- wc2 1x1 conv + relu + softmax(4) ------------------------
__global__ void k_wc2_softmax(const float* __restrict__ w, const float* __restrict__ bias)
{
    __shared__ float sw[256];
    __shared__ float sb[4];
    int t = threadIdx.x;
    if (t < 256) sw[t] = w[t];
    if (t < 4)   sb[t] = bias[t];
    __syncthreads();
    int m = blockIdx.x * 256 + t;
    const float* hr = g_h + (size_t)m * 64;
    float a0 = sb[0], a1 = sb[1], a2 = sb[2], a3 = sb[3];
#pragma unroll 4
    for (int c = 0; c < 64; c++) {
        float hv = hr[c];
        a0 = fmaf(sw[c], hv, a0);
        a1 = fmaf(sw[64 + c], hv, a1);
        a2 = fmaf(sw[128 + c], hv, a2);
        a3 = fmaf(sw[192 + c], hv, a3);
    }
    a0 = fmaxf(a0, 0.f); a1 = fmaxf(a1, 0.f); a2 = fmaxf(a2, 0.f); a3 = fmaxf(a3, 0.f);
    float mx = fmaxf(fmaxf(a0, a1), fmaxf(a2, a3));
    float e0 = __expf(a0 - mx), e1 = __expf(a1 - mx), e2 = __expf(a2 - mx), e3 = __expf(a3 - mx);
    float r = 1.0f / (e0 + e1 + e2 + e3);
    g_wmap[(size_t)m * 4 + 0] = e0 * r;
    g_wmap[(size_t)m * 4 + 1] = e1 * r;
    g_wmap[(size_t)m * 4 + 2] = e2 * r;
    g_wmap[(size_t)m * 4 + 3] = e3 * r;
}

// ---------------- scale feat1 (already in g_acc) by wmap[:,0] -------------
__global__ void k_scale0()
{
    int idx = blockIdx.x * 256 + threadIdx.x;
    g_acc[idx] *= g_wmap[(size_t)(idx >> 6) * 4];
}

// ---------------- final transpose (m,c) -> NCHW ---------------------------
__global__ void k_transpose_out(float* __restrict__ out)
{
    __shared__ float tile[32][33];
    int b = blockIdx.z;
    int c0 = blockIdx.y * 32;
    int m0 = blockIdx.x * 32;
    int tx = threadIdx.x, ty = threadIdx.y;
#pragma unroll
    for (int i = 0; i < 4; i++) {
        int mm = m0 + ty + i * 8;
        tile[ty + i * 8][tx] = g_acc[((size_t)b * 16384 + mm) * 64 + c0 + tx];
    }
    __syncthreads();
#pragma unroll
    for (int i = 0; i < 4; i++) {
        int cc = c0 + ty + i * 8;
        out[((size_t)b * 64 + cc) * 16384 + m0 + tx] = tile[tx][ty + i * 8];
    }
}

// ---------------- launch ---------------------------------------------------
extern "C" void kernel_launch(void* const* d_in, const int* /*in_sizes*/, int /*n_in*/,
                              void* d_out, int /*out_size*/)
{
    const float* bg    = (const float*)d_in[0];
    const float* fg    = (const float*)d_in[1];
    const float* dil_w = (const float*)d_in[2];
    const float* dil_b = (const float*)d_in[3];
    const float* wc1_w = (const float*)d_in[4];
    const float* wc1_b = (const float*)d_in[5];
    const float* wc2_w = (const float*)d_in[6];
    const float* wc2_b = (const float*)d_in[7];
    float* out = (float*)d_out;

    __nv_bfloat16 *pPth, *pPtl, *pXh, *pXl, *pWh, *pWl;
    float *pS, *pAcc, *pWmap;
    cudaGetSymbolAddress((void**)&pPth,  g_Pth);
    cudaGetSymbolAddress((void**)&pPtl,  g_Ptl);
    cudaGetSymbolAddress((void**)&pS,    g_S);
    cudaGetSymbolAddress((void**)&pXh,   g_xh);
    cudaGetSymbolAddress((void**)&pXl,   g_xl);
    cudaGetSymbolAddress((void**)&pWh,   g_Wh);
    cudaGetSymbolAddress((void**)&pWl,   g_Wl);
    cudaGetSymbolAddress((void**)&pAcc,  g_acc);
    cudaGetSymbolAddress((void**)&pWmap, g_wmap);

    const int SM128 = 2 * (2 * 128 * 80 + 2 * 128 * 80);   // 81920
    const int SM64  = 2 * (2 * 128 * 80 + 2 * 64 * 80);    // 61440
    cudaFuncSetAttribute(k_hgemm_sym<128, 128>, cudaFuncAttributeMaxDynamicSharedMemorySize, SM128);
    cudaFuncSetAttribute(k_conv<128, 0>, cudaFuncAttributeMaxDynamicSharedMemorySize, SM128);
    cudaFuncSetAttribute(k_conv<64, 1>,  cudaFuncAttributeMaxDynamicSharedMemorySize, SM64);

    // ---- RAL ----
    k_resize<<<(B_ * C_ * HS * HS + 255) / 256, 256>>>(fg);
    k_build_Pt<<<(int)(((size_t)B_ * NP * KP + 255) / 256), 256>>>();

    // S = Pt * Pt^T (Gram, symmetric: 528 upper-tri blocks + mirror)
    k_hgemm_sym<128, 128><<<dim3(528, 1, B_), 256, SM128>>>(
        pPth, pPtl, pS, KP, KP, NP,
        (size_t)NP * KP, (size_t)NP * NP);

    k_norms<<<(B_ * NP + 255) / 256, 256>>>();
    k_softmax_sparse<<<B_ * NP, 256>>>();

    k_build_Bg<<<(int)(((size_t)B_ * NP * 1024 + 255) / 256), 256>>>(bg);
    k_colsum_part<<<dim3(4, 16, B_), 256>>>();
    k_colsum_red<<<16, 256>>>();

    k_sparseU<<<B_ * NP, 256>>>();
    k_col2im_nhwc<<<(B_ * H_ * W_ * C_) / 256, 256>>>();

    // ---- MSFA ----
    k_wsplit_conv<<<(C_ * KC + 255) / 256, 256>>>(wc1_w, 0);
    k_wsplit_conv<<<(C_ * KC + 255) / 256, 256>>>(dil_w, 64);
    k_conv<128, 0><<<MC / 128, 256, SM128>>>(
        pXh, pXl, pWh, pWl, nullptr, wc1_b, dil_b, nullptr, 0, 1);

    k_wc2_softmax<<<MC / 256, 256>>>(wc2_w, wc2_b);
    k_scale0<<<(MC * 64) / 256, 256>>>();

    for (int i = 1; i < 4; i++) {
        k_wsplit_conv<<<(C_ * KC + 255) / 256, 256>>>(dil_w + (size_t)i * KC * C_, 0);
        k_conv<64, 1><<<MC / 128, 128, SM64>>>(
            pXh, pXl, pWh, pWl, pAcc, dil_b + i * C_, nullptr,
            pWmap, i, 1 << i);
    }

    k_transpose_out<<<dim3(16384 / 32, 2, B_), dim3(32, 8)>>>(out);
}